// round 1
// baseline (speedup 1.0000x reference)
#include <cuda_runtime.h>
#include <math.h>

#define DIMN 64
#define HID 32
#define BATCH 1024
#define DH 2048   // DIMN*HID
#define LOG2PI_F 1.8378770664093453f

// ---------------- scratch (device globals; no allocation allowed) ----------------
// per flow: wn0 (DH*DIMN) + wn1 (DH*DH) + wn2 (DIMN*DH)
__device__ float g_wn[3 * ((size_t)DH*DIMN + (size_t)DH*DH + (size_t)DIMN*DH)];
__device__ float g_t1[BATCH*DH];
__device__ float g_d1[BATCH*DH];
__device__ float g_t2[BATCH*DH];
__device__ float g_d2[BATCH*DH];
__device__ float g_h3[BATCH*DIMN];
__device__ float g_xa[BATCH*DIMN];
__device__ float g_xb[BATCH*DIMN];
__device__ float g_ldjc[BATCH*DIMN];
__device__ float g_ldj[BATCH];

// ---------------- weight preprocessing ----------------
// w = exp(W) on diag blocks, W on strictly-lower blocks, 0 above.
// wn = exp(dw) * w / sqrt(rowsum(w^2)).  One block per output row.
__global__ void prep_kernel(const float* __restrict__ W, const float* __restrict__ dw,
                            float* __restrict__ wn, int out_f, int in_f) {
    extern __shared__ float sw[];
    __shared__ float red[8];
    int o = blockIdx.x;
    int ob = out_f / DIMN, ib = in_f / DIMN;
    int bi = o / ob;
    int dlo = bi * ib, dhi = dlo + ib;
    const float* Wr = W + (size_t)o * in_f;
    float ss = 0.f;
    for (int j = threadIdx.x; j < in_f; j += blockDim.x) {
        float Wv = Wr[j];
        float w = (j >= dhi) ? 0.f : ((j >= dlo) ? expf(Wv) : Wv);
        sw[j] = w;
        ss += w * w;
    }
    #pragma unroll
    for (int off = 16; off; off >>= 1) ss += __shfl_down_sync(0xffffffffu, ss, off);
    if ((threadIdx.x & 31) == 0) red[threadIdx.x >> 5] = ss;
    __syncthreads();
    if (threadIdx.x == 0) {
        float v = 0.f;
        int nw = (int)(blockDim.x >> 5);
        for (int w = 0; w < nw; w++) v += red[w];
        red[0] = v;
    }
    __syncthreads();
    float scale = expf(dw[o]) / sqrtf(red[0]);
    float* wnr = wn + (size_t)o * in_f;
    for (int j = threadIdx.x; j < in_f; j += blockDim.x) wnr[j] = sw[j] * scale;
}

// ---------------- GEMM: C[M,N] = A[M,K] @ Bw[N,K]^T + bias ----------------
// MODE 0: store tanh(v) -> T and 1-t^2 -> D.   MODE 1: store raw v -> T.
template<int BM, int BN, int BK, int TM, int TN, int MODE>
__global__ void gemm_kernel(const float* __restrict__ A, const float* __restrict__ Bw,
                            const float* __restrict__ bias,
                            float* __restrict__ T, float* __restrict__ D,
                            int K, int N) {
    constexpr int THREADS = (BM * BN) / (TM * TN);
    __shared__ float As[BK][BM];
    __shared__ float Bs[BK][BN];
    const int tid  = threadIdx.x;
    const int tcol = tid % (BN / TN);
    const int trow = tid / (BN / TN);
    const int m0 = blockIdx.y * BM;
    const int n0 = blockIdx.x * BN;

    float acc[TM][TN];
    #pragma unroll
    for (int i = 0; i < TM; i++)
        #pragma unroll
        for (int j = 0; j < TN; j++) acc[i][j] = 0.f;

    for (int k0 = 0; k0 < K; k0 += BK) {
        #pragma unroll
        for (int idx = tid; idx < BM * BK; idx += THREADS) {
            int m = idx / BK, kk = idx % BK;
            As[kk][m] = A[(size_t)(m0 + m) * K + k0 + kk];
        }
        #pragma unroll
        for (int idx = tid; idx < BN * BK; idx += THREADS) {
            int n = idx / BK, kk = idx % BK;
            Bs[kk][n] = Bw[(size_t)(n0 + n) * K + k0 + kk];
        }
        __syncthreads();
        #pragma unroll
        for (int kk = 0; kk < BK; kk++) {
            float ar[TM], br[TN];
            #pragma unroll
            for (int i = 0; i < TM; i++) ar[i] = As[kk][trow * TM + i];
            #pragma unroll
            for (int j = 0; j < TN; j++) br[j] = Bs[kk][tcol * TN + j];
            #pragma unroll
            for (int i = 0; i < TM; i++)
                #pragma unroll
                for (int j = 0; j < TN; j++)
                    acc[i][j] = fmaf(ar[i], br[j], acc[i][j]);
        }
        __syncthreads();
    }

    #pragma unroll
    for (int i = 0; i < TM; i++) {
        int m = m0 + trow * TM + i;
        #pragma unroll
        for (int j = 0; j < TN; j++) {
            int n = n0 + tcol * TN + j;
            float v = acc[i][j] + bias[n];
            if constexpr (MODE == 0) {
                float t = tanhf(v);
                T[(size_t)m * N + n] = t;
                D[(size_t)m * N + n] = 1.f - t * t;
            } else {
                T[(size_t)m * N + n] = v;
            }
        }
    }
}

// ---------------- Jacobian chain (linear domain) ----------------
// For (batch b, dim i): J = w2diag(i) . ( d2_blk * ( W1diag(i) @ (d1_blk * v0(i)) ) )
// One warp per (b,i); 8 warps/block share the SMEM-cached 32x32 diag block.
__global__ void grad_kernel(const float* __restrict__ wn0, const float* __restrict__ wn1,
                            const float* __restrict__ wn2,
                            const float* __restrict__ d1, const float* __restrict__ d2,
                            const float* __restrict__ gate, int use_gate,
                            float* __restrict__ ldjc) {
    __shared__ float s_w1[HID][HID + 1];   // pad: avoid 32-way bank conflict
    __shared__ float s_v0[HID];
    __shared__ float s_w2[HID];
    int i = blockIdx.x;
    int tid = threadIdx.x;
    for (int idx = tid; idx < HID * HID; idx += blockDim.x) {
        int r = idx >> 5, c = idx & 31;
        s_w1[r][c] = wn1[(size_t)(i * HID + r) * DH + i * HID + c];
    }
    if (tid < HID) {
        s_v0[tid] = wn0[(size_t)(i * HID + tid) * DIMN + i];   // ib=1 -> column i
        s_w2[tid] = wn2[(size_t)i * DH + i * HID + tid];       // ob=1 -> row i
    }
    __syncthreads();
    int warp = tid >> 5, lane = tid & 31;
    int b = blockIdx.y * (blockDim.x >> 5) + warp;

    float u1 = s_v0[lane] * d1[(size_t)b * DH + i * HID + lane];
    float acc = 0.f;
    #pragma unroll
    for (int k = 0; k < HID; k++) {
        float uk = __shfl_sync(0xffffffffu, u1, k);
        acc = fmaf(s_w1[lane][k], uk, acc);
    }
    float term = s_w2[lane] * (acc * d2[(size_t)b * DH + i * HID + lane]);
    #pragma unroll
    for (int off = 16; off; off >>= 1) term += __shfl_down_sync(0xffffffffu, term, off);
    if (lane == 0) {
        float J = term;   // strictly positive
        float c;
        if (use_gate) {
            float g = gate[0];
            // softplus(logJ + g) - softplus(g) = log1p(J*e^g) - log1p(e^g)
            c = log1pf(J * expf(g)) - log1pf(expf(g));
        } else {
            c = logf(J);
        }
        ldjc[(size_t)b * DIMN + i] = c;
    }
}

// ---------------- gate mix + reversal + ldj reduction / final density ----------------
__global__ void mix_kernel(const float* __restrict__ h3, const float* __restrict__ xin,
                           const float* __restrict__ ldjc, const float* __restrict__ gate,
                           int flow, float* __restrict__ xout, float* __restrict__ ldj,
                           float* __restrict__ out_final) {
    int warp = threadIdx.x >> 5, lane = threadIdx.x & 31;
    int b = blockIdx.x * (blockDim.x >> 5) + warp;
    float sum = ldjc[(size_t)b * DIMN + lane] + ldjc[(size_t)b * DIMN + 32 + lane];
    if (flow < 2) {
        float gv = gate[0];
        float s = 1.f / (1.f + expf(-gv));
        float o0 = s * h3[b * DIMN + lane]      + (1.f - s) * xin[b * DIMN + lane];
        float o1 = s * h3[b * DIMN + 32 + lane] + (1.f - s) * xin[b * DIMN + 32 + lane];
        // x = x[:, ::-1]
        xout[b * DIMN + (DIMN - 1 - lane)]        = o0;
        xout[b * DIMN + (DIMN - 1 - (32 + lane))] = o1;
    } else {
        float o0 = h3[b * DIMN + lane], o1 = h3[b * DIMN + 32 + lane];
        sum += -0.5f * (o0 * o0 + o1 * o1) - LOG2PI_F;  // 2 dims per lane
    }
    #pragma unroll
    for (int off = 16; off; off >>= 1) sum += __shfl_down_sync(0xffffffffu, sum, off);
    if (lane == 0) {
        if (flow == 0)      ldj[b] = sum;
        else if (flow == 1) ldj[b] += sum;
        else                out_final[b] = ldj[b] + sum;
    }
}

// ---------------- launch ----------------
extern "C" void kernel_launch(void* const* d_in, const int* in_sizes, int n_in,
                              void* d_out, int out_size) {
    const float* x = (const float*)d_in[0];
    const float* gates[2] = { (const float*)d_in[28], (const float*)d_in[29] };

    float *wn_base, *t1, *d1, *t2, *d2, *h3, *xa, *xb, *ldjc, *ldj;
    cudaGetSymbolAddress((void**)&wn_base, g_wn);
    cudaGetSymbolAddress((void**)&t1,   g_t1);
    cudaGetSymbolAddress((void**)&d1,   g_d1);
    cudaGetSymbolAddress((void**)&t2,   g_t2);
    cudaGetSymbolAddress((void**)&d2,   g_d2);
    cudaGetSymbolAddress((void**)&h3,   g_h3);
    cudaGetSymbolAddress((void**)&xa,   g_xa);
    cudaGetSymbolAddress((void**)&xb,   g_xb);
    cudaGetSymbolAddress((void**)&ldjc, g_ldjc);
    cudaGetSymbolAddress((void**)&ldj,  g_ldj);

    const size_t SZ0 = (size_t)DH * DIMN;
    const size_t SZ1 = (size_t)DH * DH;
    const size_t SZ2 = (size_t)DIMN * DH;
    const size_t FSZ = SZ0 + SZ1 + SZ2;

    // 1) preprocess all weights (independent of x)
    for (int f = 0; f < 3; f++) {
        const float* W0  = (const float*)d_in[1 + f * 9 + 0];
        const float* dw0 = (const float*)d_in[1 + f * 9 + 1];
        const float* W1  = (const float*)d_in[1 + f * 9 + 3];
        const float* dw1 = (const float*)d_in[1 + f * 9 + 4];
        const float* W2  = (const float*)d_in[1 + f * 9 + 6];
        const float* dw2 = (const float*)d_in[1 + f * 9 + 7];
        float* base = wn_base + f * FSZ;
        prep_kernel<<<DH,   256, DIMN * sizeof(float)>>>(W0, dw0, base,             DH,   DIMN);
        prep_kernel<<<DH,   256, DH   * sizeof(float)>>>(W1, dw1, base + SZ0,       DH,   DH);
        prep_kernel<<<DIMN, 256, DH   * sizeof(float)>>>(W2, dw2, base + SZ0 + SZ1, DIMN, DH);
    }

    // 2) flows (sequential)
    const float* xcur = x;
    for (int f = 0; f < 3; f++) {
        float* wn0 = wn_base + f * FSZ;
        float* wn1 = wn0 + SZ0;
        float* wn2 = wn1 + SZ1;
        const float* b0 = (const float*)d_in[1 + f * 9 + 2];
        const float* b1 = (const float*)d_in[1 + f * 9 + 5];
        const float* b2 = (const float*)d_in[1 + f * 9 + 8];

        // layer0: M=1024, N=2048, K=64  (fused tanh + tanh')
        gemm_kernel<64, 64, 16, 4, 4, 0><<<dim3(DH / 64, BATCH / 64), 256>>>(
            xcur, wn0, b0, t1, d1, DIMN, DH);
        // layer1: M=1024, N=2048, K=2048
        gemm_kernel<64, 64, 16, 4, 4, 0><<<dim3(DH / 64, BATCH / 64), 256>>>(
            t1, wn1, b1, t2, d2, DH, DH);
        // layer2: M=1024, N=64, K=2048  (raw output)
        gemm_kernel<16, 64, 16, 1, 4, 1><<<dim3(1, BATCH / 16), 256>>>(
            t2, wn2, b2, h3, nullptr, DH, DIMN);

        // Jacobian chain per (batch, dim)
        grad_kernel<<<dim3(DIMN, BATCH / 8), 256>>>(
            wn0, wn1, wn2, d1, d2,
            (f < 2) ? gates[f] : nullptr, (f < 2) ? 1 : 0, ldjc);

        // gate mix + reverse + ldj accumulate (final flow: write log_p to d_out)
        float* xnext = (f == 0) ? xa : xb;
        mix_kernel<<<BATCH / 8, 256>>>(
            h3, xcur, ldjc, (f < 2) ? gates[f] : nullptr, f,
            xnext, ldj, (float*)d_out);
        xcur = xnext;
    }
}

// round 2
// speedup vs baseline: 2.0003x; 2.0003x over previous
#include <cuda_runtime.h>
#include <math.h>

#define DIMN 64
#define HID 32
#define BATCH 1024
#define DH 2048   // DIMN*HID
#define LOG2PI_F 1.8378770664093453f

// ---------------- scratch (device globals; no allocation allowed) ----------------
__device__ float g_wn[3 * ((size_t)DH*DIMN + (size_t)DH*DH + (size_t)DIMN*DH)];
__device__ float g_t1[BATCH*DH];
__device__ float g_d1[BATCH*DH];
__device__ float g_t2[BATCH*DH];
__device__ float g_d2[BATCH*DH];
__device__ float g_h3[BATCH*DIMN];
__device__ float g_xa[BATCH*DIMN];
__device__ float g_xb[BATCH*DIMN];
__device__ float g_ldjc[BATCH*DIMN];
__device__ float g_ldj[BATCH];

// ---------------- packed f32x2 helpers ----------------
__device__ __forceinline__ void fma2(unsigned long long& d, unsigned long long a,
                                     unsigned long long b) {
    asm("fma.rn.f32x2 %0, %1, %2, %3;" : "=l"(d) : "l"(a), "l"(b), "l"(d));
}
__device__ __forceinline__ unsigned long long dup2(float v) {
    unsigned long long r;
    asm("mov.b64 %0, {%1, %1};" : "=l"(r) : "f"(v));
    return r;
}

// ---------------- weight preprocessing ----------------
__global__ void prep_kernel(const float* __restrict__ W, const float* __restrict__ dw,
                            float* __restrict__ wn, int out_f, int in_f) {
    extern __shared__ float sw[];
    __shared__ float red[8];
    int o = blockIdx.x;
    int ob = out_f / DIMN, ib = in_f / DIMN;
    int bi = o / ob;
    int dlo = bi * ib, dhi = dlo + ib;
    const float* Wr = W + (size_t)o * in_f;
    float ss = 0.f;
    for (int j = threadIdx.x; j < in_f; j += blockDim.x) {
        float Wv = Wr[j];
        float w = (j >= dhi) ? 0.f : ((j >= dlo) ? expf(Wv) : Wv);
        sw[j] = w;
        ss += w * w;
    }
    #pragma unroll
    for (int off = 16; off; off >>= 1) ss += __shfl_down_sync(0xffffffffu, ss, off);
    if ((threadIdx.x & 31) == 0) red[threadIdx.x >> 5] = ss;
    __syncthreads();
    if (threadIdx.x == 0) {
        float v = 0.f;
        int nw = (int)(blockDim.x >> 5);
        for (int w = 0; w < nw; w++) v += red[w];
        red[0] = v;
    }
    __syncthreads();
    float scale = expf(dw[o]) / sqrtf(red[0]);
    float* wnr = wn + (size_t)o * in_f;
    for (int j = threadIdx.x; j < in_f; j += blockDim.x) wnr[j] = sw[j] * scale;
}

// ---------------- big GEMM: C[M,N] = A[M,K] @ Bw[N,K]^T + bias ----------------
// BM=128, BN=64, BK=16, 256 threads, microtile 8x4, FFMA2 inner loop,
// double-buffered smem (1 sync per k-tile).
// MODE 0: T = tanh(v), D = 1 - t^2.
template<int MODE>
__global__ void __launch_bounds__(256, 2)
gemm_ffma2(const float* __restrict__ A, const float* __restrict__ Bw,
           const float* __restrict__ bias,
           float* __restrict__ T, float* __restrict__ D,
           int K, int N) {
    const int BM = 128, BN = 64, BK = 16;
    __shared__ float As[2][BK][BM + 4];   // stride 132 floats (16B aligned)
    __shared__ float Bs[2][BK][BN + 4];   // stride 68 floats  (16B aligned)

    const int tid  = threadIdx.x;
    const int tcol = tid & 15;   // 16 col groups of 4
    const int trow = tid >> 4;   // 16 row groups of 8
    const int m0 = blockIdx.y * BM;
    const int n0 = blockIdx.x * BN;

    // global-load mapping
    const int rA = tid >> 2;           // 0..63 (two rows: rA, rA+64)
    const int kA = (tid & 3) * 4;      // 0,4,8,12
    const int rB = tid >> 2;           // 0..63
    const int kB = (tid & 3) * 4;

    const float* pA0 = A  + (size_t)(m0 + rA) * K + kA;
    const float* pA1 = A  + (size_t)(m0 + rA + 64) * K + kA;
    const float* pB  = Bw + (size_t)(n0 + rB) * K + kB;

    unsigned long long acc[4][4];   // [row-pair][col], rows 2rp,2rp+1 packed
    #pragma unroll
    for (int i = 0; i < 4; i++)
        #pragma unroll
        for (int j = 0; j < 4; j++) acc[i][j] = 0ull;

    // preload tile 0
    {
        float4 a0 = *(const float4*)pA0;
        float4 a1 = *(const float4*)pA1;
        float4 b0 = *(const float4*)pB;
        As[0][kA+0][rA] = a0.x; As[0][kA+1][rA] = a0.y;
        As[0][kA+2][rA] = a0.z; As[0][kA+3][rA] = a0.w;
        As[0][kA+0][rA+64] = a1.x; As[0][kA+1][rA+64] = a1.y;
        As[0][kA+2][rA+64] = a1.z; As[0][kA+3][rA+64] = a1.w;
        Bs[0][kB+0][rB] = b0.x; Bs[0][kB+1][rB] = b0.y;
        Bs[0][kB+2][rB] = b0.z; Bs[0][kB+3][rB] = b0.w;
    }
    __syncthreads();

    const int nk = K / BK;
    for (int t = 0; t < nk; t++) {
        float4 a0, a1, b0;
        if (t + 1 < nk) {
            a0 = *(const float4*)(pA0 + (t + 1) * BK);
            a1 = *(const float4*)(pA1 + (t + 1) * BK);
            b0 = *(const float4*)(pB  + (t + 1) * BK);
        }
        const int cur = t & 1;
        #pragma unroll
        for (int kk = 0; kk < BK; kk++) {
            const ulonglong2* pa = (const ulonglong2*)&As[cur][kk][trow * 8];
            ulonglong2 a01 = pa[0];
            ulonglong2 a23 = pa[1];
            float4 bv = *(const float4*)&Bs[cur][kk][tcol * 4];
            unsigned long long bb0 = dup2(bv.x), bb1 = dup2(bv.y),
                               bb2 = dup2(bv.z), bb3 = dup2(bv.w);
            fma2(acc[0][0], a01.x, bb0); fma2(acc[0][1], a01.x, bb1);
            fma2(acc[0][2], a01.x, bb2); fma2(acc[0][3], a01.x, bb3);
            fma2(acc[1][0], a01.y, bb0); fma2(acc[1][1], a01.y, bb1);
            fma2(acc[1][2], a01.y, bb2); fma2(acc[1][3], a01.y, bb3);
            fma2(acc[2][0], a23.x, bb0); fma2(acc[2][1], a23.x, bb1);
            fma2(acc[2][2], a23.x, bb2); fma2(acc[2][3], a23.x, bb3);
            fma2(acc[3][0], a23.y, bb0); fma2(acc[3][1], a23.y, bb1);
            fma2(acc[3][2], a23.y, bb2); fma2(acc[3][3], a23.y, bb3);
        }
        if (t + 1 < nk) {
            const int nxt = cur ^ 1;
            As[nxt][kA+0][rA] = a0.x; As[nxt][kA+1][rA] = a0.y;
            As[nxt][kA+2][rA] = a0.z; As[nxt][kA+3][rA] = a0.w;
            As[nxt][kA+0][rA+64] = a1.x; As[nxt][kA+1][rA+64] = a1.y;
            As[nxt][kA+2][rA+64] = a1.z; As[nxt][kA+3][rA+64] = a1.w;
            Bs[nxt][kB+0][rB] = b0.x; Bs[nxt][kB+1][rB] = b0.y;
            Bs[nxt][kB+2][rB] = b0.z; Bs[nxt][kB+3][rB] = b0.w;
            __syncthreads();
        }
    }

    // epilogue
    const int ncol = n0 + tcol * 4;
    float4 bv = *(const float4*)&bias[ncol];
    float bcol[4] = { bv.x, bv.y, bv.z, bv.w };
    #pragma unroll
    for (int i = 0; i < 8; i++) {
        const int m = m0 + trow * 8 + i;
        const int rp = i >> 1, e = i & 1;
        float4 tv, dv;
        float vr[4];
        #pragma unroll
        for (int c = 0; c < 4; c++)
            vr[c] = ((const float*)&acc[rp][c])[e] + bcol[c];
        if constexpr (MODE == 0) {
            float t0 = tanhf(vr[0]), t1 = tanhf(vr[1]),
                  t2 = tanhf(vr[2]), t3 = tanhf(vr[3]);
            tv = make_float4(t0, t1, t2, t3);
            dv = make_float4(1.f - t0*t0, 1.f - t1*t1, 1.f - t2*t2, 1.f - t3*t3);
            *(float4*)&T[(size_t)m * N + ncol] = tv;
            *(float4*)&D[(size_t)m * N + ncol] = dv;
        } else {
            tv = make_float4(vr[0], vr[1], vr[2], vr[3]);
            *(float4*)&T[(size_t)m * N + ncol] = tv;
        }
    }
}

// ---------------- small GEMM for layer2 (M=1024, N=64, K=2048) ----------------
template<int BM, int BN, int BK, int TM, int TN>
__global__ void gemm_small(const float* __restrict__ A, const float* __restrict__ Bw,
                           const float* __restrict__ bias,
                           float* __restrict__ T, int K, int N) {
    constexpr int THREADS = (BM * BN) / (TM * TN);
    __shared__ float As[BK][BM];
    __shared__ float Bs[BK][BN];
    const int tid  = threadIdx.x;
    const int tcol = tid % (BN / TN);
    const int trow = tid / (BN / TN);
    const int m0 = blockIdx.y * BM;
    const int n0 = blockIdx.x * BN;

    float acc[TM][TN];
    #pragma unroll
    for (int i = 0; i < TM; i++)
        #pragma unroll
        for (int j = 0; j < TN; j++) acc[i][j] = 0.f;

    for (int k0 = 0; k0 < K; k0 += BK) {
        #pragma unroll
        for (int idx = tid; idx < BM * BK; idx += THREADS) {
            int m = idx / BK, kk = idx % BK;
            As[kk][m] = A[(size_t)(m0 + m) * K + k0 + kk];
        }
        #pragma unroll
        for (int idx = tid; idx < BN * BK; idx += THREADS) {
            int n = idx / BK, kk = idx % BK;
            Bs[kk][n] = Bw[(size_t)(n0 + n) * K + k0 + kk];
        }
        __syncthreads();
        #pragma unroll
        for (int kk = 0; kk < BK; kk++) {
            float ar[TM], br[TN];
            #pragma unroll
            for (int i = 0; i < TM; i++) ar[i] = As[kk][trow * TM + i];
            #pragma unroll
            for (int j = 0; j < TN; j++) br[j] = Bs[kk][tcol * TN + j];
            #pragma unroll
            for (int i = 0; i < TM; i++)
                #pragma unroll
                for (int j = 0; j < TN; j++)
                    acc[i][j] = fmaf(ar[i], br[j], acc[i][j]);
        }
        __syncthreads();
    }
    #pragma unroll
    for (int i = 0; i < TM; i++) {
        int m = m0 + trow * TM + i;
        #pragma unroll
        for (int j = 0; j < TN; j++) {
            int n = n0 + tcol * TN + j;
            T[(size_t)m * N + n] = acc[i][j] + bias[n];
        }
    }
}

// ---------------- Jacobian chain (linear domain) ----------------
__global__ void grad_kernel(const float* __restrict__ wn0, const float* __restrict__ wn1,
                            const float* __restrict__ wn2,
                            const float* __restrict__ d1, const float* __restrict__ d2,
                            const float* __restrict__ gate, int use_gate,
                            float* __restrict__ ldjc) {
    __shared__ float s_w1[HID][HID + 1];
    __shared__ float s_v0[HID];
    __shared__ float s_w2[HID];
    int i = blockIdx.x;
    int tid = threadIdx.x;
    for (int idx = tid; idx < HID * HID; idx += blockDim.x) {
        int r = idx >> 5, c = idx & 31;
        s_w1[r][c] = wn1[(size_t)(i * HID + r) * DH + i * HID + c];
    }
    if (tid < HID) {
        s_v0[tid] = wn0[(size_t)(i * HID + tid) * DIMN + i];
        s_w2[tid] = wn2[(size_t)i * DH + i * HID + tid];
    }
    __syncthreads();
    int warp = tid >> 5, lane = tid & 31;
    int b = blockIdx.y * (blockDim.x >> 5) + warp;

    float u1 = s_v0[lane] * d1[(size_t)b * DH + i * HID + lane];
    float acc = 0.f;
    #pragma unroll
    for (int k = 0; k < HID; k++) {
        float uk = __shfl_sync(0xffffffffu, u1, k);
        acc = fmaf(s_w1[lane][k], uk, acc);
    }
    float term = s_w2[lane] * (acc * d2[(size_t)b * DH + i * HID + lane]);
    #pragma unroll
    for (int off = 16; off; off >>= 1) term += __shfl_down_sync(0xffffffffu, term, off);
    if (lane == 0) {
        float J = term;
        float c;
        if (use_gate) {
            float g = gate[0];
            c = log1pf(J * expf(g)) - log1pf(expf(g));
        } else {
            c = logf(J);
        }
        ldjc[(size_t)b * DIMN + i] = c;
    }
}

// ---------------- gate mix + reversal + ldj reduction / final density ----------------
__global__ void mix_kernel(const float* __restrict__ h3, const float* __restrict__ xin,
                           const float* __restrict__ ldjc, const float* __restrict__ gate,
                           int flow, float* __restrict__ xout, float* __restrict__ ldj,
                           float* __restrict__ out_final) {
    int warp = threadIdx.x >> 5, lane = threadIdx.x & 31;
    int b = blockIdx.x * (blockDim.x >> 5) + warp;
    float sum = ldjc[(size_t)b * DIMN + lane] + ldjc[(size_t)b * DIMN + 32 + lane];
    if (flow < 2) {
        float gv = gate[0];
        float s = 1.f / (1.f + expf(-gv));
        float o0 = s * h3[b * DIMN + lane]      + (1.f - s) * xin[b * DIMN + lane];
        float o1 = s * h3[b * DIMN + 32 + lane] + (1.f - s) * xin[b * DIMN + 32 + lane];
        xout[b * DIMN + (DIMN - 1 - lane)]        = o0;
        xout[b * DIMN + (DIMN - 1 - (32 + lane))] = o1;
    } else {
        float o0 = h3[b * DIMN + lane], o1 = h3[b * DIMN + 32 + lane];
        sum += -0.5f * (o0 * o0 + o1 * o1) - LOG2PI_F;
    }
    #pragma unroll
    for (int off = 16; off; off >>= 1) sum += __shfl_down_sync(0xffffffffu, sum, off);
    if (lane == 0) {
        if (flow == 0)      ldj[b] = sum;
        else if (flow == 1) ldj[b] += sum;
        else                out_final[b] = ldj[b] + sum;
    }
}

// ---------------- launch ----------------
extern "C" void kernel_launch(void* const* d_in, const int* in_sizes, int n_in,
                              void* d_out, int out_size) {
    const float* x = (const float*)d_in[0];
    const float* gates[2] = { (const float*)d_in[28], (const float*)d_in[29] };

    float *wn_base, *t1, *d1, *t2, *d2, *h3, *xa, *xb, *ldjc, *ldj;
    cudaGetSymbolAddress((void**)&wn_base, g_wn);
    cudaGetSymbolAddress((void**)&t1,   g_t1);
    cudaGetSymbolAddress((void**)&d1,   g_d1);
    cudaGetSymbolAddress((void**)&t2,   g_t2);
    cudaGetSymbolAddress((void**)&d2,   g_d2);
    cudaGetSymbolAddress((void**)&h3,   g_h3);
    cudaGetSymbolAddress((void**)&xa,   g_xa);
    cudaGetSymbolAddress((void**)&xb,   g_xb);
    cudaGetSymbolAddress((void**)&ldjc, g_ldjc);
    cudaGetSymbolAddress((void**)&ldj,  g_ldj);

    const size_t SZ0 = (size_t)DH * DIMN;
    const size_t SZ1 = (size_t)DH * DH;
    const size_t SZ2 = (size_t)DIMN * DH;
    const size_t FSZ = SZ0 + SZ1 + SZ2;

    for (int f = 0; f < 3; f++) {
        const float* W0  = (const float*)d_in[1 + f * 9 + 0];
        const float* dw0 = (const float*)d_in[1 + f * 9 + 1];
        const float* W1  = (const float*)d_in[1 + f * 9 + 3];
        const float* dw1 = (const float*)d_in[1 + f * 9 + 4];
        const float* W2  = (const float*)d_in[1 + f * 9 + 6];
        const float* dw2 = (const float*)d_in[1 + f * 9 + 7];
        float* base = wn_base + f * FSZ;
        prep_kernel<<<DH,   256, DIMN * sizeof(float)>>>(W0, dw0, base,             DH,   DIMN);
        prep_kernel<<<DH,   256, DH   * sizeof(float)>>>(W1, dw1, base + SZ0,       DH,   DH);
        prep_kernel<<<DIMN, 256, DH   * sizeof(float)>>>(W2, dw2, base + SZ0 + SZ1, DIMN, DH);
    }

    const float* xcur = x;
    for (int f = 0; f < 3; f++) {
        float* wn0 = wn_base + f * FSZ;
        float* wn1 = wn0 + SZ0;
        float* wn2 = wn1 + SZ1;
        const float* b0 = (const float*)d_in[1 + f * 9 + 2];
        const float* b1 = (const float*)d_in[1 + f * 9 + 5];
        const float* b2 = (const float*)d_in[1 + f * 9 + 8];

        // layer0: M=1024, N=2048, K=64  (fused tanh + tanh')
        gemm_ffma2<0><<<dim3(DH / 64, BATCH / 128), 256>>>(xcur, wn0, b0, t1, d1, DIMN, DH);
        // layer1: M=1024, N=2048, K=2048 (fused tanh + tanh')
        gemm_ffma2<0><<<dim3(DH / 64, BATCH / 128), 256>>>(t1, wn1, b1, t2, d2, DH, DH);
        // layer2: M=1024, N=64, K=2048  (raw output)
        gemm_small<16, 64, 16, 1, 4><<<dim3(1, BATCH / 16), 256>>>(t2, wn2, b2, h3, DH, DIMN);

        grad_kernel<<<dim3(DIMN, BATCH / 8), 256>>>(
            wn0, wn1, wn2, d1, d2,
            (f < 2) ? gates[f] : nullptr, (f < 2) ? 1 : 0, ldjc);

        float* xnext = (f == 0) ? xa : xb;
        mix_kernel<<<BATCH / 8, 256>>>(
            h3, xcur, ldjc, (f < 2) ? gates[f] : nullptr, f,
            xnext, ldj, (float*)d_out);
        xcur = xnext;
    }
}

// round 4
// speedup vs baseline: 4.4864x; 2.2428x over previous
#include <cuda_runtime.h>
#include <cuda_bf16.h>
#include <math.h>
#include <stdint.h>

#define DIMN 64
#define HID 32
#define BATCH 1024
#define DH 2048   // DIMN*HID
#define LOG2PI_F 1.8378770664093453f

// ---------------- scratch (device globals; no allocation allowed) ----------------
__device__ float g_wn[3 * ((size_t)DH*DIMN + (size_t)DH*DH + (size_t)DIMN*DH)];
__device__ __nv_bfloat16 g_w1h[3 * (size_t)DH * DH];
__device__ __nv_bfloat16 g_w1l[3 * (size_t)DH * DH];
__device__ __nv_bfloat16 g_t1h[(size_t)BATCH * DH];
__device__ __nv_bfloat16 g_t1l[(size_t)BATCH * DH];
__device__ float g_d1[BATCH*DH];
__device__ float g_t2[BATCH*DH];
__device__ float g_d2[BATCH*DH];
__device__ float g_part[8 * BATCH * DIMN];
__device__ float g_h3[BATCH*DIMN];
__device__ float g_xa[BATCH*DIMN];
__device__ float g_xb[BATCH*DIMN];
__device__ float g_ldjc[BATCH*DIMN];
__device__ float g_ldj[BATCH];

// ---------------- helpers ----------------
__device__ __forceinline__ uint32_t smem_u32(const void* p) {
    uint32_t a;
    asm("{ .reg .u64 t; cvta.to.shared.u64 t, %1; cvt.u32.u64 %0, t; }" : "=r"(a) : "l"(p));
    return a;
}
__device__ __forceinline__ void cp_async16(uint32_t dst, const void* src) {
    asm volatile("cp.async.cg.shared.global [%0], [%1], 16;" :: "r"(dst), "l"(src) : "memory");
}
__device__ __forceinline__ void cp_commit() {
    asm volatile("cp.async.commit_group;" ::: "memory");
}
#define CP_WAIT(n) asm volatile("cp.async.wait_group %0;" :: "n"(n) : "memory")

#define LDSM4(r, a) \
    asm volatile("ldmatrix.sync.aligned.m8n8.x4.shared.b16 {%0,%1,%2,%3}, [%4];" \
        : "=r"((r)[0]), "=r"((r)[1]), "=r"((r)[2]), "=r"((r)[3]) : "r"(a))

__device__ __forceinline__ void mma_bf16(float* c, const uint32_t* a, const uint32_t* b) {
    asm volatile("mma.sync.aligned.m16n8k16.row.col.f32.bf16.bf16.f32 "
                 "{%0,%1,%2,%3}, {%4,%5,%6,%7}, {%8,%9}, {%0,%1,%2,%3};"
                 : "+f"(c[0]), "+f"(c[1]), "+f"(c[2]), "+f"(c[3])
                 : "r"(a[0]), "r"(a[1]), "r"(a[2]), "r"(a[3]), "r"(b[0]), "r"(b[1]));
}

// ---------------- packed f32x2 helpers ----------------
__device__ __forceinline__ void fma2(unsigned long long& d, unsigned long long a,
                                     unsigned long long b) {
    asm("fma.rn.f32x2 %0, %1, %2, %3;" : "=l"(d) : "l"(a), "l"(b), "l"(d));
}
__device__ __forceinline__ unsigned long long dup2(float v) {
    unsigned long long r;
    asm("mov.b64 %0, {%1, %1};" : "=l"(r) : "f"(v));
    return r;
}
__device__ __forceinline__ void split_bf16(float v, __nv_bfloat16& h, __nv_bfloat16& l) {
    h = __float2bfloat16(v);
    l = __float2bfloat16(v - __bfloat162float(h));
}

// ---------------- weight preprocessing ----------------
__global__ void prep_kernel(const float* __restrict__ W, const float* __restrict__ dw,
                            float* __restrict__ wn,
                            __nv_bfloat16* __restrict__ wh, __nv_bfloat16* __restrict__ wl,
                            int out_f, int in_f) {
    extern __shared__ float sw[];
    __shared__ float red[8];
    int o = blockIdx.x;
    int ob = out_f / DIMN, ib = in_f / DIMN;
    int bi = o / ob;
    int dlo = bi * ib, dhi = dlo + ib;
    const float* Wr = W + (size_t)o * in_f;
    float ss = 0.f;
    for (int j = threadIdx.x; j < in_f; j += blockDim.x) {
        float Wv = Wr[j];
        float w = (j >= dhi) ? 0.f : ((j >= dlo) ? expf(Wv) : Wv);
        sw[j] = w;
        ss += w * w;
    }
    #pragma unroll
    for (int off = 16; off; off >>= 1) ss += __shfl_down_sync(0xffffffffu, ss, off);
    if ((threadIdx.x & 31) == 0) red[threadIdx.x >> 5] = ss;
    __syncthreads();
    if (threadIdx.x == 0) {
        float v = 0.f;
        int nw = (int)(blockDim.x >> 5);
        for (int w = 0; w < nw; w++) v += red[w];
        red[0] = v;
    }
    __syncthreads();
    float scale = expf(dw[o]) / sqrtf(red[0]);
    float* wnr = wn + (size_t)o * in_f;
    for (int j = threadIdx.x; j < in_f; j += blockDim.x) {
        float v = sw[j] * scale;
        wnr[j] = v;
        if (wh) {
            __nv_bfloat16 h, l;
            split_bf16(v, h, l);
            wh[(size_t)o * in_f + j] = h;
            wl[(size_t)o * in_f + j] = l;
        }
    }
}

// ---------------- layer0 GEMM (FFMA2): out = x @ wn0^T, K=64 ----------------
__global__ void __launch_bounds__(256, 2)
gemm_l0(const float* __restrict__ A, const float* __restrict__ Bw,
        const float* __restrict__ bias,
        __nv_bfloat16* __restrict__ Th, __nv_bfloat16* __restrict__ Tl,
        float* __restrict__ D, int K, int N) {
    const int BM = 128, BK = 16;
    __shared__ float As[2][BK][BM + 4];
    __shared__ float Bs[2][BK][64 + 4];

    const int tid  = threadIdx.x;
    const int tcol = tid & 15;
    const int trow = tid >> 4;
    const int m0 = blockIdx.y * BM;
    const int n0 = blockIdx.x * 64;

    const int rA = tid >> 2;
    const int kA = (tid & 3) * 4;
    const float* pA0 = A  + (size_t)(m0 + rA) * K + kA;
    const float* pA1 = A  + (size_t)(m0 + rA + 64) * K + kA;
    const float* pB  = Bw + (size_t)(n0 + rA) * K + kA;

    unsigned long long acc[4][4];
    #pragma unroll
    for (int i = 0; i < 4; i++)
        #pragma unroll
        for (int j = 0; j < 4; j++) acc[i][j] = 0ull;

    {
        float4 a0 = *(const float4*)pA0;
        float4 a1 = *(const float4*)pA1;
        float4 b0 = *(const float4*)pB;
        As[0][kA+0][rA] = a0.x; As[0][kA+1][rA] = a0.y;
        As[0][kA+2][rA] = a0.z; As[0][kA+3][rA] = a0.w;
        As[0][kA+0][rA+64] = a1.x; As[0][kA+1][rA+64] = a1.y;
        As[0][kA+2][rA+64] = a1.z; As[0][kA+3][rA+64] = a1.w;
        Bs[0][kA+0][rA] = b0.x; Bs[0][kA+1][rA] = b0.y;
        Bs[0][kA+2][rA] = b0.z; Bs[0][kA+3][rA] = b0.w;
    }
    __syncthreads();

    const int nk = K / BK;
    for (int t = 0; t < nk; t++) {
        float4 a0, a1, b0;
        if (t + 1 < nk) {
            a0 = *(const float4*)(pA0 + (t + 1) * BK);
            a1 = *(const float4*)(pA1 + (t + 1) * BK);
            b0 = *(const float4*)(pB  + (t + 1) * BK);
        }
        const int cur = t & 1;
        #pragma unroll
        for (int kk = 0; kk < BK; kk++) {
            const ulonglong2* pa = (const ulonglong2*)&As[cur][kk][trow * 8];
            ulonglong2 a01 = pa[0];
            ulonglong2 a23 = pa[1];
            float4 bv = *(const float4*)&Bs[cur][kk][tcol * 4];
            unsigned long long bb0 = dup2(bv.x), bb1 = dup2(bv.y),
                               bb2 = dup2(bv.z), bb3 = dup2(bv.w);
            fma2(acc[0][0], a01.x, bb0); fma2(acc[0][1], a01.x, bb1);
            fma2(acc[0][2], a01.x, bb2); fma2(acc[0][3], a01.x, bb3);
            fma2(acc[1][0], a01.y, bb0); fma2(acc[1][1], a01.y, bb1);
            fma2(acc[1][2], a01.y, bb2); fma2(acc[1][3], a01.y, bb3);
            fma2(acc[2][0], a23.x, bb0); fma2(acc[2][1], a23.x, bb1);
            fma2(acc[2][2], a23.x, bb2); fma2(acc[2][3], a23.x, bb3);
            fma2(acc[3][0], a23.y, bb0); fma2(acc[3][1], a23.y, bb1);
            fma2(acc[3][2], a23.y, bb2); fma2(acc[3][3], a23.y, bb3);
        }
        if (t + 1 < nk) {
            const int nxt = cur ^ 1;
            As[nxt][kA+0][rA] = a0.x; As[nxt][kA+1][rA] = a0.y;
            As[nxt][kA+2][rA] = a0.z; As[nxt][kA+3][rA] = a0.w;
            As[nxt][kA+0][rA+64] = a1.x; As[nxt][kA+1][rA+64] = a1.y;
            As[nxt][kA+2][rA+64] = a1.z; As[nxt][kA+3][rA+64] = a1.w;
            Bs[nxt][kA+0][rA] = b0.x; Bs[nxt][kA+1][rA] = b0.y;
            Bs[nxt][kA+2][rA] = b0.z; Bs[nxt][kA+3][rA] = b0.w;
            __syncthreads();
        }
    }

    const int ncol = n0 + tcol * 4;
    float4 bv = *(const float4*)&bias[ncol];
    float bcol[4] = { bv.x, bv.y, bv.z, bv.w };
    #pragma unroll
    for (int i = 0; i < 8; i++) {
        const int m = m0 + trow * 8 + i;
        const int rp = i >> 1, e = i & 1;
        float vr[4], tv[4];
        #pragma unroll
        for (int c = 0; c < 4; c++) {
            vr[c] = ((const float*)&acc[rp][c])[e] + bcol[c];
            tv[c] = tanhf(vr[c]);
        }
        float4 dv = make_float4(1.f - tv[0]*tv[0], 1.f - tv[1]*tv[1],
                                1.f - tv[2]*tv[2], 1.f - tv[3]*tv[3]);
        *(float4*)&D[(size_t)m * N + ncol] = dv;
        #pragma unroll
        for (int c = 0; c < 4; c++) {
            __nv_bfloat16 h, l;
            split_bf16(tv[c], h, l);
            Th[(size_t)m * N + ncol + c] = h;
            Tl[(size_t)m * N + ncol + c] = l;
        }
    }
}

// ---------------- layer1 HMMA GEMM (split-bf16 x3 mma.sync) ----------------
// C[1024,2048] = A @ B^T + bias; T=tanh(C), Dd=1-T^2.
// CTA 128x128, BK=32, 3-stage cp.async, warp grid 2(m) x 4(n), warp tile 64x32.
__global__ void __launch_bounds__(256, 1)
gemm_mma_l1(const __nv_bfloat16* __restrict__ Ah, const __nv_bfloat16* __restrict__ Al,
            const __nv_bfloat16* __restrict__ Bh, const __nv_bfloat16* __restrict__ Bl,
            const float* __restrict__ bias,
            float* __restrict__ T, float* __restrict__ Dd) {
    extern __shared__ char smem[];
    const int K = DH, N = DH;
    const int tid = threadIdx.x, lane = tid & 31, wid = tid >> 5;
    const int warpM = wid & 1, warpN = wid >> 1;   // 2 x 4
    const int m0 = blockIdx.y * 128, n0 = blockIdx.x * 128;
    const uint32_t sbase = smem_u32(smem);

    const __nv_bfloat16* gptr[4] = {
        Ah + (size_t)m0 * K, Al + (size_t)m0 * K,
        Bh + (size_t)n0 * K, Bl + (size_t)n0 * K
    };

    float acc[4][4][4];
    #pragma unroll
    for (int i = 0; i < 4; i++)
        #pragma unroll
        for (int j = 0; j < 4; j++)
            #pragma unroll
            for (int e = 0; e < 4; e++) acc[i][j][e] = 0.f;

    // cp.async prefetch of k-tile t into stage t%3 (Ah|Al|Bh|Bl, 8KB each)
    const int pr_row = (tid >> 2);          // base row for j=0 chunk (ci>>2)
    const int pr_ch  = (tid & 3);
    #define PREFETCH(t) do {                                                     \
        uint32_t stb = sbase + ((t) % 3) * 32768;                                \
        _Pragma("unroll")                                                        \
        for (int a = 0; a < 4; a++) {                                            \
            _Pragma("unroll")                                                    \
            for (int j = 0; j < 2; j++) {                                        \
                int row = pr_row + j * 64;                                       \
                int ch  = pr_ch;                                                 \
                const __nv_bfloat16* src = gptr[a] + (size_t)row * K + (t) * 32 + ch * 8; \
                uint32_t dst = stb + a * 8192 + row * 64 + ((ch ^ ((row >> 1) & 3)) * 16); \
                cp_async16(dst, src);                                            \
            }                                                                    \
        }                                                                        \
        cp_commit();                                                             \
    } while (0)

    PREFETCH(0);
    PREFETCH(1);

    const int rlA = warpM * 64 + (lane & 15);
    const int rlB = warpN * 32 + (lane & 15);
    const int hi  = lane >> 4;
    const int xA  = (rlA >> 1) & 3;
    const int xB  = (rlB >> 1) & 3;

    const int NK = K / 32;   // 64
    for (int t = 0; t < NK; t++) {
        CP_WAIT(1);
        __syncthreads();
        if (t + 2 < NK) PREFETCH(t + 2);

        const uint32_t stb = sbase + (t % 3) * 32768;
        const uint32_t pAh = stb + rlA * 64;
        const uint32_t pAl = pAh + 8192;
        const uint32_t pBh = stb + 16384 + rlB * 64;
        const uint32_t pBl = pBh + 8192;

        #pragma unroll
        for (int ks = 0; ks < 2; ks++) {
            const uint32_t cA = (uint32_t)(((ks * 2 + hi) ^ xA) * 16);
            const uint32_t cB = (uint32_t)(((ks * 2 + hi) ^ xB) * 16);
            uint32_t ah[4][4], al[4][4], bh[4][2], bl[4][2];
            #pragma unroll
            for (int mt = 0; mt < 4; mt++) {
                LDSM4(ah[mt], pAh + mt * 1024 + cA);
                LDSM4(al[mt], pAl + mt * 1024 + cA);
            }
            #pragma unroll
            for (int p = 0; p < 2; p++) {
                uint32_t r[4];
                LDSM4(r, pBh + p * 1024 + cB);
                bh[2*p][0] = r[0]; bh[2*p+1][0] = r[1];
                bh[2*p][1] = r[2]; bh[2*p+1][1] = r[3];
                LDSM4(r, pBl + p * 1024 + cB);
                bl[2*p][0] = r[0]; bl[2*p+1][0] = r[1];
                bl[2*p][1] = r[2]; bl[2*p+1][1] = r[3];
            }
            #pragma unroll
            for (int mt = 0; mt < 4; mt++)
                #pragma unroll
                for (int nt = 0; nt < 4; nt++) {
                    mma_bf16(acc[mt][nt], ah[mt], bh[nt]);
                    mma_bf16(acc[mt][nt], ah[mt], bl[nt]);
                    mma_bf16(acc[mt][nt], al[mt], bh[nt]);
                }
        }
    }

    // epilogue: bias + tanh, direct stores
    const int er = lane >> 2, ec = (lane & 3) * 2;
    #pragma unroll
    for (int nt = 0; nt < 4; nt++) {
        const int col = n0 + warpN * 32 + nt * 8 + ec;
        const float2 bv = *(const float2*)&bias[col];
        #pragma unroll
        for (int mt = 0; mt < 4; mt++) {
            const int r0 = m0 + warpM * 64 + mt * 16 + er;
            float t00 = tanhf(acc[mt][nt][0] + bv.x);
            float t01 = tanhf(acc[mt][nt][1] + bv.y);
            float t10 = tanhf(acc[mt][nt][2] + bv.x);
            float t11 = tanhf(acc[mt][nt][3] + bv.y);
            *(float2*)&T[(size_t)r0 * N + col]        = make_float2(t00, t01);
            *(float2*)&T[(size_t)(r0 + 8) * N + col]  = make_float2(t10, t11);
            *(float2*)&Dd[(size_t)r0 * N + col]       = make_float2(1.f - t00*t00, 1.f - t01*t01);
            *(float2*)&Dd[(size_t)(r0 + 8) * N + col] = make_float2(1.f - t10*t10, 1.f - t11*t11);
        }
    }
}

// ---------------- layer2 split-K partial GEMM (M=1024, N=64, K=2048) ----------------
__global__ void gemm_l2_partial(const float* __restrict__ A, const float* __restrict__ Bw,
                                float* __restrict__ part) {
    const int BM = 64, BN = 64, BK = 16, TM = 4, TN = 4;
    __shared__ float As[BK][BM];
    __shared__ float Bs[BK][BN];
    const int tid  = threadIdx.x;
    const int tcol = tid % (BN / TN);
    const int trow = tid / (BN / TN);
    const int kp = blockIdx.x;
    const int m0 = blockIdx.y * BM;
    const int kbeg = kp * 256, kend = kbeg + 256;

    float acc[TM][TN];
    #pragma unroll
    for (int i = 0; i < TM; i++)
        #pragma unroll
        for (int j = 0; j < TN; j++) acc[i][j] = 0.f;

    for (int k0 = kbeg; k0 < kend; k0 += BK) {
        #pragma unroll
        for (int idx = tid; idx < BM * BK; idx += 256) {
            int m = idx / BK, kk = idx % BK;
            As[kk][m] = A[(size_t)(m0 + m) * DH + k0 + kk];
        }
        #pragma unroll
        for (int idx = tid; idx < BN * BK; idx += 256) {
            int n = idx / BK, kk = idx % BK;
            Bs[kk][n] = Bw[(size_t)n * DH + k0 + kk];
        }
        __syncthreads();
        #pragma unroll
        for (int kk = 0; kk < BK; kk++) {
            float ar[TM], br[TN];
            #pragma unroll
            for (int i = 0; i < TM; i++) ar[i] = As[kk][trow * TM + i];
            #pragma unroll
            for (int j = 0; j < TN; j++) br[j] = Bs[kk][tcol * TN + j];
            #pragma unroll
            for (int i = 0; i < TM; i++)
                #pragma unroll
                for (int j = 0; j < TN; j++)
                    acc[i][j] = fmaf(ar[i], br[j], acc[i][j]);
        }
        __syncthreads();
    }
    #pragma unroll
    for (int i = 0; i < TM; i++) {
        int m = m0 + trow * TM + i;
        #pragma unroll
        for (int j = 0; j < TN; j++) {
            int n = tcol * TN + j;
            part[(size_t)kp * BATCH * DIMN + (size_t)m * DIMN + n] = acc[i][j];
        }
    }
}

__global__ void l2_reduce(const float* __restrict__ part, const float* __restrict__ bias,
                          float* __restrict__ h3) {
    int idx = blockIdx.x * blockDim.x + threadIdx.x;
    int n = idx & (DIMN - 1);
    float s = bias[n];
    #pragma unroll
    for (int kp = 0; kp < 8; kp++) s += part[(size_t)kp * BATCH * DIMN + idx];
    h3[idx] = s;
}

// ---------------- Jacobian chain (linear domain) ----------------
__global__ void grad_kernel(const float* __restrict__ wn0, const float* __restrict__ wn1,
                            const float* __restrict__ wn2,
                            const float* __restrict__ d1, const float* __restrict__ d2,
                            const float* __restrict__ gate, int use_gate,
                            float* __restrict__ ldjc) {
    __shared__ float s_w1[HID][HID + 1];
    __shared__ float s_v0[HID];
    __shared__ float s_w2[HID];
    int i = blockIdx.x;
    int tid = threadIdx.x;
    for (int idx = tid; idx < HID * HID; idx += blockDim.x) {
        int r = idx >> 5, c = idx & 31;
        s_w1[r][c] = wn1[(size_t)(i * HID + r) * DH + i * HID + c];
    }
    if (tid < HID) {
        s_v0[tid] = wn0[(size_t)(i * HID + tid) * DIMN + i];
        s_w2[tid] = wn2[(size_t)i * DH + i * HID + tid];
    }
    __syncthreads();
    int warp = tid >> 5, lane = tid & 31;
    int b = blockIdx.y * (blockDim.x >> 5) + warp;

    float u1 = s_v0[lane] * d1[(size_t)b * DH + i * HID + lane];
    float acc = 0.f;
    #pragma unroll
    for (int k = 0; k < HID; k++) {
        float uk = __shfl_sync(0xffffffffu, u1, k);
        acc = fmaf(s_w1[lane][k], uk, acc);
    }
    float term = s_w2[lane] * (acc * d2[(size_t)b * DH + i * HID + lane]);
    #pragma unroll
    for (int off = 16; off; off >>= 1) term += __shfl_down_sync(0xffffffffu, term, off);
    if (lane == 0) {
        float J = term;
        float c;
        if (use_gate) {
            float g = gate[0];
            c = log1pf(J * expf(g)) - log1pf(expf(g));
        } else {
            c = logf(J);
        }
        ldjc[(size_t)b * DIMN + i] = c;
    }
}

// ---------------- gate mix + reversal + ldj reduction / final density ----------------
__global__ void mix_kernel(const float* __restrict__ h3, const float* __restrict__ xin,
                           const float* __restrict__ ldjc, const float* __restrict__ gate,
                           int flow, float* __restrict__ xout, float* __restrict__ ldj,
                           float* __restrict__ out_final) {
    int warp = threadIdx.x >> 5, lane = threadIdx.x & 31;
    int b = blockIdx.x * (blockDim.x >> 5) + warp;
    float sum = ldjc[(size_t)b * DIMN + lane] + ldjc[(size_t)b * DIMN + 32 + lane];
    if (flow < 2) {
        float gv = gate[0];
        float s = 1.f / (1.f + expf(-gv));
        float o0 = s * h3[b * DIMN + lane]      + (1.f - s) * xin[b * DIMN + lane];
        float o1 = s * h3[b * DIMN + 32 + lane] + (1.f - s) * xin[b * DIMN + 32 + lane];
        xout[b * DIMN + (DIMN - 1 - lane)]        = o0;
        xout[b * DIMN + (DIMN - 1 - (32 + lane))] = o1;
    } else {
        float o0 = h3[b * DIMN + lane], o1 = h3[b * DIMN + 32 + lane];
        sum += -0.5f * (o0 * o0 + o1 * o1) - LOG2PI_F;
    }
    #pragma unroll
    for (int off = 16; off; off >>= 1) sum += __shfl_down_sync(0xffffffffu, sum, off);
    if (lane == 0) {
        if (flow == 0)      ldj[b] = sum;
        else if (flow == 1) ldj[b] += sum;
        else                out_final[b] = ldj[b] + sum;
    }
}

// ---------------- launch ----------------
extern "C" void kernel_launch(void* const* d_in, const int* in_sizes, int n_in,
                              void* d_out, int out_size) {
    const float* x = (const float*)d_in[0];
    const float* gates[2] = { (const float*)d_in[28], (const float*)d_in[29] };

    float *wn_base, *d1, *t2, *d2, *h3, *xa, *xb, *ldjc, *ldj, *part;
    __nv_bfloat16 *w1h, *w1l, *t1h, *t1l;
    cudaGetSymbolAddress((void**)&wn_base, g_wn);
    cudaGetSymbolAddress((void**)&w1h,  g_w1h);
    cudaGetSymbolAddress((void**)&w1l,  g_w1l);
    cudaGetSymbolAddress((void**)&t1h,  g_t1h);
    cudaGetSymbolAddress((void**)&t1l,  g_t1l);
    cudaGetSymbolAddress((void**)&d1,   g_d1);
    cudaGetSymbolAddress((void**)&t2,   g_t2);
    cudaGetSymbolAddress((void**)&d2,   g_d2);
    cudaGetSymbolAddress((void**)&h3,   g_h3);
    cudaGetSymbolAddress((void**)&xa,   g_xa);
    cudaGetSymbolAddress((void**)&xb,   g_xb);
    cudaGetSymbolAddress((void**)&ldjc, g_ldjc);
    cudaGetSymbolAddress((void**)&ldj,  g_ldj);
    cudaGetSymbolAddress((void**)&part, g_part);

    const size_t SZ0 = (size_t)DH * DIMN;
    const size_t SZ1 = (size_t)DH * DH;
    const size_t SZ2 = (size_t)DIMN * DH;
    const size_t FSZ = SZ0 + SZ1 + SZ2;

    const int DYN_SMEM = 3 * 32768;
    static int configured = 0;
    cudaFuncSetAttribute(gemm_mma_l1, cudaFuncAttributeMaxDynamicSharedMemorySize, DYN_SMEM);
    (void)configured;

    for (int f = 0; f < 3; f++) {
        const float* W0  = (const float*)d_in[1 + f * 9 + 0];
        const float* dw0 = (const float*)d_in[1 + f * 9 + 1];
        const float* W1  = (const float*)d_in[1 + f * 9 + 3];
        const float* dw1 = (const float*)d_in[1 + f * 9 + 4];
        const float* W2  = (const float*)d_in[1 + f * 9 + 6];
        const float* dw2 = (const float*)d_in[1 + f * 9 + 7];
        float* base = wn_base + f * FSZ;
        prep_kernel<<<DH,   256, DIMN * sizeof(float)>>>(W0, dw0, base, nullptr, nullptr, DH, DIMN);
        prep_kernel<<<DH,   256, DH   * sizeof(float)>>>(W1, dw1, base + SZ0,
                                                         w1h + f * SZ1, w1l + f * SZ1, DH, DH);
        prep_kernel<<<DIMN, 256, DH   * sizeof(float)>>>(W2, dw2, base + SZ0 + SZ1,
                                                         nullptr, nullptr, DIMN, DH);
    }

    const float* xcur = x;
    for (int f = 0; f < 3; f++) {
        float* wn0 = wn_base + f * FSZ;
        float* wn2 = wn0 + SZ0 + SZ1;
        const float* b0 = (const float*)d_in[1 + f * 9 + 2];
        const float* b1 = (const float*)d_in[1 + f * 9 + 5];
        const float* b2 = (const float*)d_in[1 + f * 9 + 8];

        // layer0: M=1024, N=2048, K=64 -> t1 (bf16 hi/lo) + d1 (f32)
        gemm_l0<<<dim3(DH / 64, BATCH / 128), 256>>>(xcur, wn0, b0, t1h, t1l, d1, DIMN, DH);
        // layer1 (HMMA split-bf16): -> t2 (f32) + d2 (f32)
        gemm_mma_l1<<<dim3(DH / 128, BATCH / 128), 256, DYN_SMEM>>>(
            t1h, t1l, w1h + f * SZ1, w1l + f * SZ1, b1, t2, d2);
        // layer2: split-K partials + reduce -> h3
        gemm_l2_partial<<<dim3(8, BATCH / 64), 256>>>(t2, wn2, part);
        l2_reduce<<<(BATCH * DIMN) / 256, 256>>>(part, b2, h3);

        grad_kernel<<<dim3(DIMN, BATCH / 8), 256>>>(
            wn0, wn0 + SZ0, wn2, d1, d2,
            (f < 2) ? gates[f] : nullptr, (f < 2) ? 1 : 0, ldjc);

        float* xnext = (f == 0) ? xa : xb;
        mix_kernel<<<BATCH / 8, 256>>>(
            h3, xcur, ldjc, (f < 2) ? gates[f] : nullptr, f,
            xnext, ldj, (float*)d_out);
        xcur = xnext;
    }
}

// round 6
// speedup vs baseline: 5.4453x; 1.2137x over previous
#include <cuda_runtime.h>
#include <cuda_bf16.h>
#include <math.h>
#include <stdint.h>

#define DIMN 64
#define HID 32
#define BATCH 1024
#define DH 2048   // DIMN*HID
#define LOG2PI_F 1.8378770664093453f

// ---------------- scratch (device globals; no allocation allowed) ----------------
// NOTE: g_w1h/g_w1l rely on static zero-initialization for the masked (zero) region:
// prep1_kernel only writes columns j < dhi; the rest is never written and stays 0.
__device__ float g_wn[3 * ((size_t)DH*DIMN + (size_t)DH*DH + (size_t)DIMN*DH)];
__device__ __nv_bfloat16 g_w1h[3 * (size_t)DH * DH];
__device__ __nv_bfloat16 g_w1l[3 * (size_t)DH * DH];
__device__ float g_w1d[3 * 64 * 32 * 32];   // compact f32 diag blocks of wn1
__device__ __nv_bfloat16 g_t1h[(size_t)BATCH * DH];
__device__ __nv_bfloat16 g_t1l[(size_t)BATCH * DH];
__device__ float g_d1[BATCH*DH];
__device__ float g_t2[BATCH*DH];
__device__ float g_d2[BATCH*DH];
__device__ float g_part[8 * BATCH * DIMN];
__device__ float g_h3[BATCH*DIMN];
__device__ float g_xa[BATCH*DIMN];
__device__ float g_xb[BATCH*DIMN];
__device__ float g_ldjc[BATCH*DIMN];
__device__ float g_ldj[BATCH];

// ---------------- helpers ----------------
__device__ __forceinline__ uint32_t smem_u32(const void* p) {
    uint32_t a;
    asm("{ .reg .u64 t; cvta.to.shared.u64 t, %1; cvt.u32.u64 %0, t; }" : "=r"(a) : "l"(p));
    return a;
}
__device__ __forceinline__ void cp_async16(uint32_t dst, const void* src) {
    asm volatile("cp.async.cg.shared.global [%0], [%1], 16;" :: "r"(dst), "l"(src) : "memory");
}
__device__ __forceinline__ void cp_commit() {
    asm volatile("cp.async.commit_group;" ::: "memory");
}
#define CP_WAIT(n) asm volatile("cp.async.wait_group %0;" :: "n"(n) : "memory")

#define LDSM4(r, a) \
    asm volatile("ldmatrix.sync.aligned.m8n8.x4.shared.b16 {%0,%1,%2,%3}, [%4];" \
        : "=r"((r)[0]), "=r"((r)[1]), "=r"((r)[2]), "=r"((r)[3]) : "r"(a))

__device__ __forceinline__ void mma_bf16(float* c, const uint32_t* a, const uint32_t* b) {
    asm volatile("mma.sync.aligned.m16n8k16.row.col.f32.bf16.bf16.f32 "
                 "{%0,%1,%2,%3}, {%4,%5,%6,%7}, {%8,%9}, {%0,%1,%2,%3};"
                 : "+f"(c[0]), "+f"(c[1]), "+f"(c[2]), "+f"(c[3])
                 : "r"(a[0]), "r"(a[1]), "r"(a[2]), "r"(a[3]), "r"(b[0]), "r"(b[1]));
}

// ---------------- packed f32x2 helpers ----------------
__device__ __forceinline__ void fma2(unsigned long long& d, unsigned long long a,
                                     unsigned long long b) {
    asm("fma.rn.f32x2 %0, %1, %2, %3;" : "=l"(d) : "l"(a), "l"(b), "l"(d));
}
__device__ __forceinline__ unsigned long long dup2(float v) {
    unsigned long long r;
    asm("mov.b64 %0, {%1, %1};" : "=l"(r) : "f"(v));
    return r;
}
__device__ __forceinline__ void split_bf16(float v, __nv_bfloat16& h, __nv_bfloat16& l) {
    h = __float2bfloat16(v);
    l = __float2bfloat16(v - __bfloat162float(h));
}

// ---------------- generic weight preprocessing (W0, W2: f32 only) ----------------
__global__ void prep_kernel(const float* __restrict__ W, const float* __restrict__ dw,
                            float* __restrict__ wn, int out_f, int in_f) {
    extern __shared__ float sw[];
    __shared__ float red[8];
    int o = blockIdx.x;
    int ob = out_f / DIMN, ib = in_f / DIMN;
    int bi = o / ob;
    int dlo = bi * ib, dhi = dlo + ib;
    const float* Wr = W + (size_t)o * in_f;
    float ss = 0.f;
    for (int j = threadIdx.x; j < in_f; j += blockDim.x) {
        float Wv = Wr[j];
        float w = (j >= dhi) ? 0.f : ((j >= dlo) ? expf(Wv) : Wv);
        sw[j] = w;
        ss += w * w;
    }
    #pragma unroll
    for (int off = 16; off; off >>= 1) ss += __shfl_down_sync(0xffffffffu, ss, off);
    if ((threadIdx.x & 31) == 0) red[threadIdx.x >> 5] = ss;
    __syncthreads();
    if (threadIdx.x == 0) {
        float v = 0.f;
        int nw = (int)(blockDim.x >> 5);
        for (int w = 0; w < nw; w++) v += red[w];
        red[0] = v;
    }
    __syncthreads();
    float scale = expf(dw[o]) / sqrtf(red[0]);
    float* wnr = wn + (size_t)o * in_f;
    for (int j = threadIdx.x; j < in_f; j += blockDim.x) wnr[j] = sw[j] * scale;
}

// ---------------- W1 preprocessing: bf16 hi/lo (cols < dhi only) + f32 diag ----------------
__global__ void prep1_kernel(const float* __restrict__ W, const float* __restrict__ dw,
                             __nv_bfloat16* __restrict__ wh, __nv_bfloat16* __restrict__ wl,
                             float* __restrict__ diag) {
    extern __shared__ float sw[];
    __shared__ float red[8];
    const int o = blockIdx.x;            // 0..2047
    const int bi = o >> 5, r = o & 31;   // ob = 32
    const int dlo = bi * 32, dhi = dlo + 32;
    const float* Wr = W + (size_t)o * DH;
    float ss = 0.f;
    for (int j = threadIdx.x; j < dhi; j += blockDim.x) {
        float Wv = Wr[j];
        float w = (j >= dlo) ? expf(Wv) : Wv;
        sw[j] = w;
        ss += w * w;
    }
    #pragma unroll
    for (int off = 16; off; off >>= 1) ss += __shfl_down_sync(0xffffffffu, ss, off);
    if ((threadIdx.x & 31) == 0) red[threadIdx.x >> 5] = ss;
    __syncthreads();
    if (threadIdx.x == 0) {
        float v = 0.f;
        int nw = (int)(blockDim.x >> 5);
        for (int w = 0; w < nw; w++) v += red[w];
        red[0] = v;
    }
    __syncthreads();
    const float scale = expf(dw[o]) / sqrtf(red[0]);
    for (int j = threadIdx.x; j < dhi; j += blockDim.x) {
        float v = sw[j] * scale;
        __nv_bfloat16 h, l;
        split_bf16(v, h, l);
        wh[(size_t)o * DH + j] = h;
        wl[(size_t)o * DH + j] = l;
    }
    if (threadIdx.x < 32)
        diag[bi * 1024 + r * 32 + threadIdx.x] = sw[dlo + threadIdx.x] * scale;
}

// ---------------- layer0 GEMM (FFMA2): out = x @ wn0^T, K=64, K-limited ----------------
__global__ void __launch_bounds__(256, 2)
gemm_l0(const float* __restrict__ A, const float* __restrict__ Bw,
        const float* __restrict__ bias,
        __nv_bfloat16* __restrict__ Th, __nv_bfloat16* __restrict__ Tl,
        float* __restrict__ D, int K, int N) {
    const int BM = 128, BK = 16;
    __shared__ float As[2][BK][BM + 4];
    __shared__ float Bs[2][BK][64 + 4];

    const int tid  = threadIdx.x;
    const int tcol = tid & 15;
    const int trow = tid >> 4;
    const int m0 = blockIdx.y * BM;
    const int nx = (int)(gridDim.x - 1 - blockIdx.x);   // longest-first ordering
    const int n0 = nx * 64;
    // wn0 rows n0..n0+63 have nonzero cols <= n0/32 + 1  ->  K_eff = 2*nx + 2
    const int keff = 2 * nx + 2;
    const int nk = (keff + BK - 1) / BK;   // 1..4

    const int rA = tid >> 2;
    const int kA = (tid & 3) * 4;
    const float* pA0 = A  + (size_t)(m0 + rA) * K + kA;
    const float* pA1 = A  + (size_t)(m0 + rA + 64) * K + kA;
    const float* pB  = Bw + (size_t)(n0 + rA) * K + kA;

    unsigned long long acc[4][4];
    #pragma unroll
    for (int i = 0; i < 4; i++)
        #pragma unroll
        for (int j = 0; j < 4; j++) acc[i][j] = 0ull;

    {
        float4 a0 = *(const float4*)pA0;
        float4 a1 = *(const float4*)pA1;
        float4 b0 = *(const float4*)pB;
        As[0][kA+0][rA] = a0.x; As[0][kA+1][rA] = a0.y;
        As[0][kA+2][rA] = a0.z; As[0][kA+3][rA] = a0.w;
        As[0][kA+0][rA+64] = a1.x; As[0][kA+1][rA+64] = a1.y;
        As[0][kA+2][rA+64] = a1.z; As[0][kA+3][rA+64] = a1.w;
        Bs[0][kA+0][rA] = b0.x; Bs[0][kA+1][rA] = b0.y;
        Bs[0][kA+2][rA] = b0.z; Bs[0][kA+3][rA] = b0.w;
    }
    __syncthreads();

    for (int t = 0; t < nk; t++) {
        float4 a0, a1, b0;
        if (t + 1 < nk) {
            a0 = *(const float4*)(pA0 + (t + 1) * BK);
            a1 = *(const float4*)(pA1 + (t + 1) * BK);
            b0 = *(const float4*)(pB  + (t + 1) * BK);
        }
        const int cur = t & 1;
        #pragma unroll
        for (int kk = 0; kk < BK; kk++) {
            const ulonglong2* pa = (const ulonglong2*)&As[cur][kk][trow * 8];
            ulonglong2 a01 = pa[0];
            ulonglong2 a23 = pa[1];
            float4 bv = *(const float4*)&Bs[cur][kk][tcol * 4];
            unsigned long long bb0 = dup2(bv.x), bb1 = dup2(bv.y),
                               bb2 = dup2(bv.z), bb3 = dup2(bv.w);
            fma2(acc[0][0], a01.x, bb0); fma2(acc[0][1], a01.x, bb1);
            fma2(acc[0][2], a01.x, bb2); fma2(acc[0][3], a01.x, bb3);
            fma2(acc[1][0], a01.y, bb0); fma2(acc[1][1], a01.y, bb1);
            fma2(acc[1][2], a01.y, bb2); fma2(acc[1][3], a01.y, bb3);
            fma2(acc[2][0], a23.x, bb0); fma2(acc[2][1], a23.x, bb1);
            fma2(acc[2][2], a23.x, bb2); fma2(acc[2][3], a23.x, bb3);
            fma2(acc[3][0], a23.y, bb0); fma2(acc[3][1], a23.y, bb1);
            fma2(acc[3][2], a23.y, bb2); fma2(acc[3][3], a23.y, bb3);
        }
        if (t + 1 < nk) {
            const int nxt = cur ^ 1;
            As[nxt][kA+0][rA] = a0.x; As[nxt][kA+1][rA] = a0.y;
            As[nxt][kA+2][rA] = a0.z; As[nxt][kA+3][rA] = a0.w;
            As[nxt][kA+0][rA+64] = a1.x; As[nxt][kA+1][rA+64] = a1.y;
            As[nxt][kA+2][rA+64] = a1.z; As[nxt][kA+3][rA+64] = a1.w;
            Bs[nxt][kA+0][rA] = b0.x; Bs[nxt][kA+1][rA] = b0.y;
            Bs[nxt][kA+2][rA] = b0.z; Bs[nxt][kA+3][rA] = b0.w;
            __syncthreads();
        }
    }

    const int ncol = n0 + tcol * 4;
    float4 bv = *(const float4*)&bias[ncol];
    float bcol[4] = { bv.x, bv.y, bv.z, bv.w };
    #pragma unroll
    for (int i = 0; i < 8; i++) {
        const int m = m0 + trow * 8 + i;
        const int rp = i >> 1, e = i & 1;
        float vr[4], tv[4];
        #pragma unroll
        for (int c = 0; c < 4; c++) {
            vr[c] = ((const float*)&acc[rp][c])[e] + bcol[c];
            tv[c] = tanhf(vr[c]);
        }
        float4 dv = make_float4(1.f - tv[0]*tv[0], 1.f - tv[1]*tv[1],
                                1.f - tv[2]*tv[2], 1.f - tv[3]*tv[3]);
        *(float4*)&D[(size_t)m * N + ncol] = dv;
        #pragma unroll
        for (int c = 0; c < 4; c++) {
            __nv_bfloat16 h, l;
            split_bf16(tv[c], h, l);
            Th[(size_t)m * N + ncol + c] = h;
            Tl[(size_t)m * N + ncol + c] = l;
        }
    }
}

// ---------------- layer1 HMMA GEMM (split-bf16, block-triangular K-early-exit) ----------
// CTA 128(M) x 64(N); grid 256 CTAs 1D, ordered longest-K-first.
__global__ void __launch_bounds__(256, 1)
gemm_mma_l1(const __nv_bfloat16* __restrict__ Ah, const __nv_bfloat16* __restrict__ Al,
            const __nv_bfloat16* __restrict__ Bh, const __nv_bfloat16* __restrict__ Bl,
            const float* __restrict__ bias,
            float* __restrict__ T, float* __restrict__ Dd) {
    extern __shared__ char smem[];
    const int K = DH, N = DH;
    const int tid = threadIdx.x, lane = tid & 31, wid = tid >> 5;
    const int warpM = wid & 1, warpN = wid >> 1;   // 2 x 4 warps, warp tile 64x16
    const int bid = blockIdx.x;
    const int jn = 31 - (bid >> 3);        // n-tile index, largest-K first
    const int mi = bid & 7;
    const int m0 = mi * 128, n0 = jn * 64;
    const int NK = min(64, 2 * jn + 4);    // k-tiles of 32 actually needed
    const uint32_t sbase = smem_u32(smem);

    const __nv_bfloat16* gA[2] = { Ah + (size_t)m0 * K, Al + (size_t)m0 * K };
    const __nv_bfloat16* gB[2] = { Bh + (size_t)n0 * K, Bl + (size_t)n0 * K };

    float acc[4][2][4];
    #pragma unroll
    for (int i = 0; i < 4; i++)
        #pragma unroll
        for (int j = 0; j < 2; j++)
            #pragma unroll
            for (int e = 0; e < 4; e++) acc[i][j][e] = 0.f;

    // stage: Ah 0..8K, Al 8K..16K, Bh 16K..20K, Bl 20K..24K  (rows of 64B, swizzled)
    const int pr_row = tid >> 2;
    const int pr_ch  = tid & 3;
    #define PREFETCH(t) do {                                                          \
        uint32_t stb = sbase + ((t) % 3) * 24576;                                     \
        _Pragma("unroll")                                                             \
        for (int a = 0; a < 2; a++) {                                                 \
            _Pragma("unroll")                                                         \
            for (int j = 0; j < 2; j++) {                                             \
                int row = pr_row + j * 64;                                            \
                const __nv_bfloat16* src = gA[a] + (size_t)row * K + (t) * 32 + pr_ch * 8; \
                uint32_t dst = stb + a * 8192 + row * 64 + ((pr_ch ^ ((row >> 1) & 3)) * 16); \
                cp_async16(dst, src);                                                 \
            }                                                                         \
            const __nv_bfloat16* srcb = gB[a] + (size_t)pr_row * K + (t) * 32 + pr_ch * 8; \
            uint32_t dstb = stb + 16384 + a * 4096 + pr_row * 64                      \
                          + ((pr_ch ^ ((pr_row >> 1) & 3)) * 16);                     \
            cp_async16(dstb, srcb);                                                   \
        }                                                                             \
        cp_commit();                                                                  \
    } while (0)

    PREFETCH(0);
    PREFETCH(1);

    const int rlA = warpM * 64 + (lane & 15);
    const int rlB = warpN * 16 + (lane & 15);
    const int hi  = lane >> 4;
    const int xA  = (rlA >> 1) & 3;
    const int xB  = (rlB >> 1) & 3;

    for (int t = 0; t < NK; t++) {
        if (t + 1 < NK) { CP_WAIT(1); } else { CP_WAIT(0); }
        __syncthreads();
        if (t + 2 < NK) PREFETCH(t + 2);

        const uint32_t stb = sbase + (t % 3) * 24576;
        const uint32_t pAh = stb + rlA * 64;
        const uint32_t pAl = pAh + 8192;
        const uint32_t pBh = stb + 16384 + rlB * 64;
        const uint32_t pBl = pBh + 4096;

        #pragma unroll
        for (int ks = 0; ks < 2; ks++) {
            const uint32_t cA = (uint32_t)(((ks * 2 + hi) ^ xA) * 16);
            const uint32_t cB = (uint32_t)(((ks * 2 + hi) ^ xB) * 16);
            uint32_t ah[4][4], al[4][4], bh[2][2], bl[2][2];
            #pragma unroll
            for (int mt = 0; mt < 4; mt++) {
                LDSM4(ah[mt], pAh + mt * 1024 + cA);
                LDSM4(al[mt], pAl + mt * 1024 + cA);
            }
            {
                uint32_t r[4];
                LDSM4(r, pBh + cB);
                bh[0][0] = r[0]; bh[1][0] = r[1];
                bh[0][1] = r[2]; bh[1][1] = r[3];
                LDSM4(r, pBl + cB);
                bl[0][0] = r[0]; bl[1][0] = r[1];
                bl[0][1] = r[2]; bl[1][1] = r[3];
            }
            #pragma unroll
            for (int mt = 0; mt < 4; mt++)
                #pragma unroll
                for (int nt = 0; nt < 2; nt++) {
                    mma_bf16(acc[mt][nt], ah[mt], bh[nt]);
                    mma_bf16(acc[mt][nt], ah[mt], bl[nt]);
                    mma_bf16(acc[mt][nt], al[mt], bh[nt]);
                }
        }
    }

    // epilogue: bias + tanh, direct stores
    const int er = lane >> 2, ec = (lane & 3) * 2;
    #pragma unroll
    for (int nt = 0; nt < 2; nt++) {
        const int col = n0 + warpN * 16 + nt * 8 + ec;
        const float2 bv = *(const float2*)&bias[col];
        #pragma unroll
        for (int mt = 0; mt < 4; mt++) {
            const int r0 = m0 + warpM * 64 + mt * 16 + er;
            float t00 = tanhf(acc[mt][nt][0] + bv.x);
            float t01 = tanhf(acc[mt][nt][1] + bv.y);
            float t10 = tanhf(acc[mt][nt][2] + bv.x);
            float t11 = tanhf(acc[mt][nt][3] + bv.y);
            *(float2*)&T[(size_t)r0 * N + col]        = make_float2(t00, t01);
            *(float2*)&T[(size_t)(r0 + 8) * N + col]  = make_float2(t10, t11);
            *(float2*)&Dd[(size_t)r0 * N + col]       = make_float2(1.f - t00*t00, 1.f - t01*t01);
            *(float2*)&Dd[(size_t)(r0 + 8) * N + col] = make_float2(1.f - t10*t10, 1.f - t11*t11);
        }
    }
}

// ---------------- layer2 split-K partial GEMM (M=1024, N=64, K=2048) ----------------
__global__ void gemm_l2_partial(const float* __restrict__ A, const float* __restrict__ Bw,
                                float* __restrict__ part) {
    const int BM = 64, BN = 64, BK = 16, TM = 4, TN = 4;
    __shared__ float As[BK][BM];
    __shared__ float Bs[BK][BN];
    const int tid  = threadIdx.x;
    const int tcol = tid % (BN / TN);
    const int trow = tid / (BN / TN);
    const int kp = blockIdx.x;
    const int m0 = blockIdx.y * BM;
    const int kbeg = kp * 256, kend = kbeg + 256;
    // wn2 row n has nonzero cols < (n+1)*32; this thread's max col = tcol*4+3
    const int kmax_thr = (tcol * 4 + 4) * 32;

    float acc[TM][TN];
    #pragma unroll
    for (int i = 0; i < TM; i++)
        #pragma unroll
        for (int j = 0; j < TN; j++) acc[i][j] = 0.f;

    for (int k0 = kbeg; k0 < kend; k0 += BK) {
        #pragma unroll
        for (int idx = tid; idx < BM * BK; idx += 256) {
            int m = idx / BK, kk = idx % BK;
            As[kk][m] = A[(size_t)(m0 + m) * DH + k0 + kk];
        }
        #pragma unroll
        for (int idx = tid; idx < BN * BK; idx += 256) {
            int n = idx / BK, kk = idx % BK;
            Bs[kk][n] = Bw[(size_t)n * DH + k0 + kk];
        }
        __syncthreads();
        if (k0 < kmax_thr) {
            #pragma unroll
            for (int kk = 0; kk < BK; kk++) {
                float ar[TM], br[TN];
                #pragma unroll
                for (int i = 0; i < TM; i++) ar[i] = As[kk][trow * TM + i];
                #pragma unroll
                for (int j = 0; j < TN; j++) br[j] = Bs[kk][tcol * TN + j];
                #pragma unroll
                for (int i = 0; i < TM; i++)
                    #pragma unroll
                    for (int j = 0; j < TN; j++)
                        acc[i][j] = fmaf(ar[i], br[j], acc[i][j]);
            }
        }
        __syncthreads();
    }
    #pragma unroll
    for (int i = 0; i < TM; i++) {
        int m = m0 + trow * TM + i;
        #pragma unroll
        for (int j = 0; j < TN; j++) {
            int n = tcol * TN + j;
            part[(size_t)kp * BATCH * DIMN + (size_t)m * DIMN + n] = acc[i][j];
        }
    }
}

__global__ void l2_reduce(const float* __restrict__ part, const float* __restrict__ bias,
                          float* __restrict__ h3) {
    int idx = blockIdx.x * blockDim.x + threadIdx.x;
    int n = idx & (DIMN - 1);
    float s = bias[n];
    #pragma unroll
    for (int kp = 0; kp < 8; kp++) s += part[(size_t)kp * BATCH * DIMN + idx];
    h3[idx] = s;
}

// ---------------- Jacobian chain (linear domain) ----------------
__global__ void grad_kernel(const float* __restrict__ wn0, const float* __restrict__ w1d,
                            const float* __restrict__ wn2,
                            const float* __restrict__ d1, const float* __restrict__ d2,
                            const float* __restrict__ gate, int use_gate,
                            float* __restrict__ ldjc) {
    __shared__ float s_w1[HID][HID + 1];
    __shared__ float s_v0[HID];
    __shared__ float s_w2[HID];
    int i = blockIdx.x;
    int tid = threadIdx.x;
    for (int idx = tid; idx < HID * HID; idx += blockDim.x) {
        int r = idx >> 5, c = idx & 31;
        s_w1[r][c] = w1d[i * 1024 + r * 32 + c];
    }
    if (tid < HID) {
        s_v0[tid] = wn0[(size_t)(i * HID + tid) * DIMN + i];
        s_w2[tid] = wn2[(size_t)i * DH + i * HID + tid];
    }
    __syncthreads();
    int warp = tid >> 5, lane = tid & 31;
    int b = blockIdx.y * (blockDim.x >> 5) + warp;

    float u1 = s_v0[lane] * d1[(size_t)b * DH + i * HID + lane];
    float acc = 0.f;
    #pragma unroll
    for (int k = 0; k < HID; k++) {
        float uk = __shfl_sync(0xffffffffu, u1, k);
        acc = fmaf(s_w1[lane][k], uk, acc);
    }
    float term = s_w2[lane] * (acc * d2[(size_t)b * DH + i * HID + lane]);
    #pragma unroll
    for (int off = 16; off; off >>= 1) term += __shfl_down_sync(0xffffffffu, term, off);
    if (lane == 0) {
        float J = term;
        float c;
        if (use_gate) {
            float g = gate[0];
            c = log1pf(J * expf(g)) - log1pf(expf(g));
        } else {
            c = logf(J);
        }
        ldjc[(size_t)b * DIMN + i] = c;
    }
}

// ---------------- gate mix + reversal + ldj reduction / final density ----------------
__global__ void mix_kernel(const float* __restrict__ h3, const float* __restrict__ xin,
                           const float* __restrict__ ldjc, const float* __restrict__ gate,
                           int flow, float* __restrict__ xout, float* __restrict__ ldj,
                           float* __restrict__ out_final) {
    int warp = threadIdx.x >> 5, lane = threadIdx.x & 31;
    int b = blockIdx.x * (blockDim.x >> 5) + warp;
    float sum = ldjc[(size_t)b * DIMN + lane] + ldjc[(size_t)b * DIMN + 32 + lane];
    if (flow < 2) {
        float gv = gate[0];
        float s = 1.f / (1.f + expf(-gv));
        float o0 = s * h3[b * DIMN + lane]      + (1.f - s) * xin[b * DIMN + lane];
        float o1 = s * h3[b * DIMN + 32 + lane] + (1.f - s) * xin[b * DIMN + 32 + lane];
        xout[b * DIMN + (DIMN - 1 - lane)]        = o0;
        xout[b * DIMN + (DIMN - 1 - (32 + lane))] = o1;
    } else {
        float o0 = h3[b * DIMN + lane], o1 = h3[b * DIMN + 32 + lane];
        sum += -0.5f * (o0 * o0 + o1 * o1) - LOG2PI_F;
    }
    #pragma unroll
    for (int off = 16; off; off >>= 1) sum += __shfl_down_sync(0xffffffffu, sum, off);
    if (lane == 0) {
        if (flow == 0)      ldj[b] = sum;
        else if (flow == 1) ldj[b] += sum;
        else                out_final[b] = ldj[b] + sum;
    }
}

// ---------------- launch ----------------
extern "C" void kernel_launch(void* const* d_in, const int* in_sizes, int n_in,
                              void* d_out, int out_size) {
    const float* x = (const float*)d_in[0];
    const float* gates[2] = { (const float*)d_in[28], (const float*)d_in[29] };

    float *wn_base, *d1, *t2, *d2, *h3, *xa, *xb, *ldjc, *ldj, *part, *w1d;
    __nv_bfloat16 *w1h, *w1l, *t1h, *t1l;
    cudaGetSymbolAddress((void**)&wn_base, g_wn);
    cudaGetSymbolAddress((void**)&w1h,  g_w1h);
    cudaGetSymbolAddress((void**)&w1l,  g_w1l);
    cudaGetSymbolAddress((void**)&w1d,  g_w1d);
    cudaGetSymbolAddress((void**)&t1h,  g_t1h);
    cudaGetSymbolAddress((void**)&t1l,  g_t1l);
    cudaGetSymbolAddress((void**)&d1,   g_d1);
    cudaGetSymbolAddress((void**)&t2,   g_t2);
    cudaGetSymbolAddress((void**)&d2,   g_d2);
    cudaGetSymbolAddress((void**)&h3,   g_h3);
    cudaGetSymbolAddress((void**)&xa,   g_xa);
    cudaGetSymbolAddress((void**)&xb,   g_xb);
    cudaGetSymbolAddress((void**)&ldjc, g_ldjc);
    cudaGetSymbolAddress((void**)&ldj,  g_ldj);
    cudaGetSymbolAddress((void**)&part, g_part);

    const size_t SZ0 = (size_t)DH * DIMN;
    const size_t SZ1 = (size_t)DH * DH;
    const size_t SZ2 = (size_t)DIMN * DH;
    const size_t FSZ = SZ0 + SZ1 + SZ2;

    const int DYN_SMEM = 3 * 24576;
    cudaFuncSetAttribute(gemm_mma_l1, cudaFuncAttributeMaxDynamicSharedMemorySize, DYN_SMEM);

    for (int f = 0; f < 3; f++) {
        const float* W0  = (const float*)d_in[1 + f * 9 + 0];
        const float* dw0 = (const float*)d_in[1 + f * 9 + 1];
        const float* W1  = (const float*)d_in[1 + f * 9 + 3];
        const float* dw1 = (const float*)d_in[1 + f * 9 + 4];
        const float* W2  = (const float*)d_in[1 + f * 9 + 6];
        const float* dw2 = (const float*)d_in[1 + f * 9 + 7];
        float* base = wn_base + f * FSZ;
        prep_kernel<<<DH,   256, DIMN * sizeof(float)>>>(W0, dw0, base, DH, DIMN);
        prep1_kernel<<<DH,  256, DH   * sizeof(float)>>>(W1, dw1,
                                                         w1h + f * SZ1, w1l + f * SZ1,
                                                         w1d + f * 64 * 1024);
        prep_kernel<<<DIMN, 256, DH   * sizeof(float)>>>(W2, dw2, base + SZ0 + SZ1, DIMN, DH);
    }

    const float* xcur = x;
    for (int f = 0; f < 3; f++) {
        float* wn0 = wn_base + f * FSZ;
        float* wn2 = wn0 + SZ0 + SZ1;
        const float* b0 = (const float*)d_in[1 + f * 9 + 2];
        const float* b1 = (const float*)d_in[1 + f * 9 + 5];
        const float* b2 = (const float*)d_in[1 + f * 9 + 8];

        // layer0: M=1024, N=2048, K<=64 (masked) -> t1 (bf16 hi/lo) + d1 (f32)
        gemm_l0<<<dim3(DH / 64, BATCH / 128), 256>>>(xcur, wn0, b0, t1h, t1l, d1, DIMN, DH);
        // layer1 (HMMA split-bf16, triangular early-exit): -> t2 (f32) + d2 (f32)
        gemm_mma_l1<<<256, 256, DYN_SMEM>>>(
            t1h, t1l, w1h + f * SZ1, w1l + f * SZ1, b1, t2, d2);
        // layer2: split-K partials + reduce -> h3
        gemm_l2_partial<<<dim3(8, BATCH / 64), 256>>>(t2, wn2, part);
        l2_reduce<<<(BATCH * DIMN) / 256, 256>>>(part, b2, h3);

        grad_kernel<<<dim3(DIMN, BATCH / 8), 256>>>(
            wn0, w1d + f * 64 * 1024, wn2, d1, d2,
            (f < 2) ? gates[f] : nullptr, (f < 2) ? 1 : 0, ldjc);

        float* xnext = (f == 0) ? xa : xb;
        mix_kernel<<<BATCH / 8, 256>>>(
            h3, xcur, ldjc, (f < 2) ? gates[f] : nullptr, f,
            xnext, ldj, (float*)d_out);
        xcur = xnext;
    }
}

// round 7
// speedup vs baseline: 5.7269x; 1.0517x over previous
#include <cuda_runtime.h>
#include <cuda_bf16.h>
#include <math.h>
#include <stdint.h>

#define DIMN 64
#define HID 32
#define BATCH 1024
#define DH 2048   // DIMN*HID
#define LOG2PI_F 1.8378770664093453f

// ---------------- scratch (device globals; no allocation allowed) ----------------
// NOTE: g_w1h/g_w1l rely on static zero-initialization for the masked (zero) region:
// prep1 only writes columns j < dhi; the rest is never written and stays 0.
__device__ float g_wn[3 * ((size_t)DH*DIMN + (size_t)DH*DH + (size_t)DIMN*DH)];
__device__ __nv_bfloat16 g_w1h[3 * (size_t)DH * DH];
__device__ __nv_bfloat16 g_w1l[3 * (size_t)DH * DH];
__device__ float g_w1d[3 * 64 * 32 * 32];   // compact f32 diag blocks of wn1
__device__ __nv_bfloat16 g_t1h[(size_t)BATCH * DH];
__device__ __nv_bfloat16 g_t1l[(size_t)BATCH * DH];
__device__ float g_d1[BATCH*DH];
__device__ float g_t2[BATCH*DH];
__device__ float g_d2[BATCH*DH];
__device__ float g_part[8 * BATCH * DIMN];
__device__ float g_h3[BATCH*DIMN];
__device__ float g_xa[BATCH*DIMN];
__device__ float g_xb[BATCH*DIMN];
__device__ float g_ldjc[BATCH*DIMN];
__device__ float g_ldj[BATCH];

struct PtrSet { const float* W[3]; const float* dw[3]; };

// ---------------- helpers ----------------
__device__ __forceinline__ uint32_t smem_u32(const void* p) {
    uint32_t a;
    asm("{ .reg .u64 t; cvta.to.shared.u64 t, %1; cvt.u32.u64 %0, t; }" : "=r"(a) : "l"(p));
    return a;
}
__device__ __forceinline__ void cp_async16(uint32_t dst, const void* src) {
    asm volatile("cp.async.cg.shared.global [%0], [%1], 16;" :: "r"(dst), "l"(src) : "memory");
}
__device__ __forceinline__ void cp_commit() {
    asm volatile("cp.async.commit_group;" ::: "memory");
}
#define CP_WAIT(n) asm volatile("cp.async.wait_group %0;" :: "n"(n) : "memory")

#define LDSM4(r, a) \
    asm volatile("ldmatrix.sync.aligned.m8n8.x4.shared.b16 {%0,%1,%2,%3}, [%4];" \
        : "=r"((r)[0]), "=r"((r)[1]), "=r"((r)[2]), "=r"((r)[3]) : "r"(a))

__device__ __forceinline__ void mma_bf16(float* c, const uint32_t* a, const uint32_t* b) {
    asm volatile("mma.sync.aligned.m16n8k16.row.col.f32.bf16.bf16.f32 "
                 "{%0,%1,%2,%3}, {%4,%5,%6,%7}, {%8,%9}, {%0,%1,%2,%3};"
                 : "+f"(c[0]), "+f"(c[1]), "+f"(c[2]), "+f"(c[3])
                 : "r"(a[0]), "r"(a[1]), "r"(a[2]), "r"(a[3]), "r"(b[0]), "r"(b[1]));
}

// ---------------- packed f32x2 helpers ----------------
__device__ __forceinline__ void fma2(unsigned long long& d, unsigned long long a,
                                     unsigned long long b) {
    asm("fma.rn.f32x2 %0, %1, %2, %3;" : "=l"(d) : "l"(a), "l"(b), "l"(d));
}
__device__ __forceinline__ unsigned long long dup2(float v) {
    unsigned long long r;
    asm("mov.b64 %0, {%1, %1};" : "=l"(r) : "f"(v));
    return r;
}
__device__ __forceinline__ void split_bf16(float v, __nv_bfloat16& h, __nv_bfloat16& l) {
    h = __float2bfloat16(v);
    l = __float2bfloat16(v - __bfloat162float(h));
}

// ---------------- prep0 (W0: 2048x64), warp-per-row, fused over 3 flows ---------------
__global__ void __launch_bounds__(256)
prep0_fused(PtrSet ps, float* __restrict__ wn_base, size_t FSZ) {
    const int f = blockIdx.y;
    const int o = blockIdx.x * 8 + (threadIdx.x >> 5);   // row 0..2047
    const int lane = threadIdx.x & 31;
    const int bi = o >> 5;                               // diag col index (ib=1)
    const float* Wr = ps.W[f] + (size_t)o * DIMN;
    float* wn = wn_base + f * FSZ + (size_t)o * DIMN;

    const int j0 = lane, j1 = lane + 32;
    float v0 = Wr[j0], v1 = Wr[j1];
    float w0 = (j0 > bi) ? 0.f : ((j0 == bi) ? expf(v0) : v0);
    float w1 = (j1 > bi) ? 0.f : ((j1 == bi) ? expf(v1) : v1);
    float ss = w0 * w0 + w1 * w1;
    #pragma unroll
    for (int off = 16; off; off >>= 1) ss += __shfl_xor_sync(0xffffffffu, ss, off);
    const float scale = expf(ps.dw[f][o]) / sqrtf(ss);
    wn[j0] = w0 * scale;
    wn[j1] = w1 * scale;
}

// ---------------- prep1 (W1: 2048x2048) -> bf16 hi/lo + f32 diag, fused --------------
__global__ void prep1_fused(PtrSet ps,
                            __nv_bfloat16* __restrict__ wh_base,
                            __nv_bfloat16* __restrict__ wl_base,
                            float* __restrict__ diag_base) {
    extern __shared__ float sw[];
    __shared__ float red[8];
    const int f = blockIdx.y;
    const int o = blockIdx.x;            // 0..2047
    const int bi = o >> 5, r = o & 31;
    const int dlo = bi * 32, dhi = dlo + 32;
    const float* Wr = ps.W[f] + (size_t)o * DH;
    __nv_bfloat16* wh = wh_base + (size_t)f * DH * DH + (size_t)o * DH;
    __nv_bfloat16* wl = wl_base + (size_t)f * DH * DH + (size_t)o * DH;
    float* diag = diag_base + f * 64 * 1024;

    float ss = 0.f;
    for (int j = threadIdx.x; j < dhi; j += blockDim.x) {
        float Wv = Wr[j];
        float w = (j >= dlo) ? expf(Wv) : Wv;
        sw[j] = w;
        ss += w * w;
    }
    #pragma unroll
    for (int off = 16; off; off >>= 1) ss += __shfl_down_sync(0xffffffffu, ss, off);
    if ((threadIdx.x & 31) == 0) red[threadIdx.x >> 5] = ss;
    __syncthreads();
    if (threadIdx.x == 0) {
        float v = 0.f;
        for (int w = 0; w < 8; w++) v += red[w];
        red[0] = v;
    }
    __syncthreads();
    const float scale = expf(ps.dw[f][o]) / sqrtf(red[0]);
    for (int j = threadIdx.x; j < dhi; j += blockDim.x) {
        float v = sw[j] * scale;
        __nv_bfloat16 h, l;
        split_bf16(v, h, l);
        wh[j] = h;
        wl[j] = l;
    }
    if (threadIdx.x < 32)
        diag[bi * 1024 + r * 32 + threadIdx.x] = sw[dlo + threadIdx.x] * scale;
}

// ---------------- prep2 (W2: 64x2048) -> f32, fused ----------------
__global__ void prep2_fused(PtrSet ps, float* __restrict__ wn_base,
                            size_t FSZ, size_t OFF) {
    extern __shared__ float sw[];
    __shared__ float red[8];
    const int f = blockIdx.y;
    const int o = blockIdx.x;            // 0..63
    const int dlo = o * 32, dhi = dlo + 32;
    const float* Wr = ps.W[f] + (size_t)o * DH;
    float* wn = wn_base + f * FSZ + OFF + (size_t)o * DH;

    float ss = 0.f;
    for (int j = threadIdx.x; j < DH; j += blockDim.x) {
        float Wv = Wr[j];
        float w = (j >= dhi) ? 0.f : ((j >= dlo) ? expf(Wv) : Wv);
        sw[j] = w;
        ss += w * w;
    }
    #pragma unroll
    for (int off = 16; off; off >>= 1) ss += __shfl_down_sync(0xffffffffu, ss, off);
    if ((threadIdx.x & 31) == 0) red[threadIdx.x >> 5] = ss;
    __syncthreads();
    if (threadIdx.x == 0) {
        float v = 0.f;
        for (int w = 0; w < 8; w++) v += red[w];
        red[0] = v;
    }
    __syncthreads();
    const float scale = expf(ps.dw[f][o]) / sqrtf(red[0]);
    for (int j = threadIdx.x; j < DH; j += blockDim.x) wn[j] = sw[j] * scale;
}

// ---------------- layer0 GEMM (FFMA2): out = x @ wn0^T, K=64, K-limited ----------------
__global__ void __launch_bounds__(256, 2)
gemm_l0(const float* __restrict__ A, const float* __restrict__ Bw,
        const float* __restrict__ bias,
        __nv_bfloat16* __restrict__ Th, __nv_bfloat16* __restrict__ Tl,
        float* __restrict__ D, int K, int N) {
    const int BM = 128, BK = 16;
    __shared__ float As[2][BK][BM + 4];
    __shared__ float Bs[2][BK][64 + 4];

    const int tid  = threadIdx.x;
    const int tcol = tid & 15;
    const int trow = tid >> 4;
    const int m0 = blockIdx.y * BM;
    const int nx = (int)(gridDim.x - 1 - blockIdx.x);   // longest-first ordering
    const int n0 = nx * 64;
    const int keff = 2 * nx + 2;
    const int nk = (keff + BK - 1) / BK;   // 1..4

    const int rA = tid >> 2;
    const int kA = (tid & 3) * 4;
    const float* pA0 = A  + (size_t)(m0 + rA) * K + kA;
    const float* pA1 = A  + (size_t)(m0 + rA + 64) * K + kA;
    const float* pB  = Bw + (size_t)(n0 + rA) * K + kA;

    unsigned long long acc[4][4];
    #pragma unroll
    for (int i = 0; i < 4; i++)
        #pragma unroll
        for (int j = 0; j < 4; j++) acc[i][j] = 0ull;

    {
        float4 a0 = *(const float4*)pA0;
        float4 a1 = *(const float4*)pA1;
        float4 b0 = *(const float4*)pB;
        As[0][kA+0][rA] = a0.x; As[0][kA+1][rA] = a0.y;
        As[0][kA+2][rA] = a0.z; As[0][kA+3][rA] = a0.w;
        As[0][kA+0][rA+64] = a1.x; As[0][kA+1][rA+64] = a1.y;
        As[0][kA+2][rA+64] = a1.z; As[0][kA+3][rA+64] = a1.w;
        Bs[0][kA+0][rA] = b0.x; Bs[0][kA+1][rA] = b0.y;
        Bs[0][kA+2][rA] = b0.z; Bs[0][kA+3][rA] = b0.w;
    }
    __syncthreads();

    for (int t = 0; t < nk; t++) {
        float4 a0, a1, b0;
        if (t + 1 < nk) {
            a0 = *(const float4*)(pA0 + (t + 1) * BK);
            a1 = *(const float4*)(pA1 + (t + 1) * BK);
            b0 = *(const float4*)(pB  + (t + 1) * BK);
        }
        const int cur = t & 1;
        #pragma unroll
        for (int kk = 0; kk < BK; kk++) {
            const ulonglong2* pa = (const ulonglong2*)&As[cur][kk][trow * 8];
            ulonglong2 a01 = pa[0];
            ulonglong2 a23 = pa[1];
            float4 bv = *(const float4*)&Bs[cur][kk][tcol * 4];
            unsigned long long bb0 = dup2(bv.x), bb1 = dup2(bv.y),
                               bb2 = dup2(bv.z), bb3 = dup2(bv.w);
            fma2(acc[0][0], a01.x, bb0); fma2(acc[0][1], a01.x, bb1);
            fma2(acc[0][2], a01.x, bb2); fma2(acc[0][3], a01.x, bb3);
            fma2(acc[1][0], a01.y, bb0); fma2(acc[1][1], a01.y, bb1);
            fma2(acc[1][2], a01.y, bb2); fma2(acc[1][3], a01.y, bb3);
            fma2(acc[2][0], a23.x, bb0); fma2(acc[2][1], a23.x, bb1);
            fma2(acc[2][2], a23.x, bb2); fma2(acc[2][3], a23.x, bb3);
            fma2(acc[3][0], a23.y, bb0); fma2(acc[3][1], a23.y, bb1);
            fma2(acc[3][2], a23.y, bb2); fma2(acc[3][3], a23.y, bb3);
        }
        if (t + 1 < nk) {
            const int nxt = cur ^ 1;
            As[nxt][kA+0][rA] = a0.x; As[nxt][kA+1][rA] = a0.y;
            As[nxt][kA+2][rA] = a0.z; As[nxt][kA+3][rA] = a0.w;
            As[nxt][kA+0][rA+64] = a1.x; As[nxt][kA+1][rA+64] = a1.y;
            As[nxt][kA+2][rA+64] = a1.z; As[nxt][kA+3][rA+64] = a1.w;
            Bs[nxt][kA+0][rA] = b0.x; Bs[nxt][kA+1][rA] = b0.y;
            Bs[nxt][kA+2][rA] = b0.z; Bs[nxt][kA+3][rA] = b0.w;
            __syncthreads();
        }
    }

    const int ncol = n0 + tcol * 4;
    float4 bv = *(const float4*)&bias[ncol];
    float bcol[4] = { bv.x, bv.y, bv.z, bv.w };
    #pragma unroll
    for (int i = 0; i < 8; i++) {
        const int m = m0 + trow * 8 + i;
        const int rp = i >> 1, e = i & 1;
        float vr[4], tv[4];
        #pragma unroll
        for (int c = 0; c < 4; c++) {
            vr[c] = ((const float*)&acc[rp][c])[e] + bcol[c];
            tv[c] = tanhf(vr[c]);
        }
        float4 dv = make_float4(1.f - tv[0]*tv[0], 1.f - tv[1]*tv[1],
                                1.f - tv[2]*tv[2], 1.f - tv[3]*tv[3]);
        *(float4*)&D[(size_t)m * N + ncol] = dv;
        #pragma unroll
        for (int c = 0; c < 4; c++) {
            __nv_bfloat16 h, l;
            split_bf16(tv[c], h, l);
            Th[(size_t)m * N + ncol + c] = h;
            Tl[(size_t)m * N + ncol + c] = l;
        }
    }
}

// ---------------- layer1 HMMA GEMM (split-bf16, block-triangular K-early-exit) ----------
// CTA 128(M) x 64(N); grid 256 CTAs 1D, longest-K-first; 2 CTAs/SM.
__global__ void __launch_bounds__(256, 2)
gemm_mma_l1(const __nv_bfloat16* __restrict__ Ah, const __nv_bfloat16* __restrict__ Al,
            const __nv_bfloat16* __restrict__ Bh, const __nv_bfloat16* __restrict__ Bl,
            const float* __restrict__ bias,
            float* __restrict__ T, float* __restrict__ Dd) {
    extern __shared__ char smem[];
    const int K = DH, N = DH;
    const int tid = threadIdx.x, lane = tid & 31, wid = tid >> 5;
    const int warpM = wid & 1, warpN = wid >> 1;   // 2 x 4 warps, warp tile 64x16
    const int bid = blockIdx.x;
    const int jn = 31 - (bid >> 3);        // n-tile index, largest-K first
    const int mi = bid & 7;
    const int m0 = mi * 128, n0 = jn * 64;
    const int NK = min(64, 2 * jn + 4);    // k-tiles of 32 actually needed
    const uint32_t sbase = smem_u32(smem);

    const __nv_bfloat16* gA[2] = { Ah + (size_t)m0 * K, Al + (size_t)m0 * K };
    const __nv_bfloat16* gB[2] = { Bh + (size_t)n0 * K, Bl + (size_t)n0 * K };

    float acc[4][2][4];
    #pragma unroll
    for (int i = 0; i < 4; i++)
        #pragma unroll
        for (int j = 0; j < 2; j++)
            #pragma unroll
            for (int e = 0; e < 4; e++) acc[i][j][e] = 0.f;

    const int pr_row = tid >> 2;
    const int pr_ch  = tid & 3;
    #define PREFETCH(t) do {                                                          \
        uint32_t stb = sbase + ((t) % 3) * 24576;                                     \
        _Pragma("unroll")                                                             \
        for (int a = 0; a < 2; a++) {                                                 \
            _Pragma("unroll")                                                         \
            for (int j = 0; j < 2; j++) {                                             \
                int row = pr_row + j * 64;                                            \
                const __nv_bfloat16* src = gA[a] + (size_t)row * K + (t) * 32 + pr_ch * 8; \
                uint32_t dst = stb + a * 8192 + row * 64 + ((pr_ch ^ ((row >> 1) & 3)) * 16); \
                cp_async16(dst, src);                                                 \
            }                                                                         \
            const __nv_bfloat16* srcb = gB[a] + (size_t)pr_row * K + (t) * 32 + pr_ch * 8; \
            uint32_t dstb = stb + 16384 + a * 4096 + pr_row * 64                      \
                          + ((pr_ch ^ ((pr_row >> 1) & 3)) * 16);                     \
            cp_async16(dstb, srcb);                                                   \
        }                                                                             \
        cp_commit();                                                                  \
    } while (0)

    PREFETCH(0);
    PREFETCH(1);

    const int rlA = warpM * 64 + (lane & 15);
    const int rlB = warpN * 16 + (lane & 15);
    const int hi  = lane >> 4;
    const int xA  = (rlA >> 1) & 3;
    const int xB  = (rlB >> 1) & 3;

    for (int t = 0; t < NK; t++) {
        if (t + 1 < NK) { CP_WAIT(1); } else { CP_WAIT(0); }
        __syncthreads();
        if (t + 2 < NK) PREFETCH(t + 2);

        const uint32_t stb = sbase + (t % 3) * 24576;
        const uint32_t pAh = stb + rlA * 64;
        const uint32_t pAl = pAh + 8192;
        const uint32_t pBh = stb + 16384 + rlB * 64;
        const uint32_t pBl = pBh + 4096;

        #pragma unroll
        for (int ks = 0; ks < 2; ks++) {
            const uint32_t cA = (uint32_t)(((ks * 2 + hi) ^ xA) * 16);
            const uint32_t cB = (uint32_t)(((ks * 2 + hi) ^ xB) * 16);
            uint32_t ah[4][4], al[4][4], bh[2][2], bl[2][2];
            #pragma unroll
            for (int mt = 0; mt < 4; mt++) {
                LDSM4(ah[mt], pAh + mt * 1024 + cA);
                LDSM4(al[mt], pAl + mt * 1024 + cA);
            }
            {
                uint32_t r[4];
                LDSM4(r, pBh + cB);
                bh[0][0] = r[0]; bh[1][0] = r[1];
                bh[0][1] = r[2]; bh[1][1] = r[3];
                LDSM4(r, pBl + cB);
                bl[0][0] = r[0]; bl[1][0] = r[1];
                bl[0][1] = r[2]; bl[1][1] = r[3];
            }
            #pragma unroll
            for (int mt = 0; mt < 4; mt++)
                #pragma unroll
                for (int nt = 0; nt < 2; nt++) {
                    mma_bf16(acc[mt][nt], ah[mt], bh[nt]);
                    mma_bf16(acc[mt][nt], ah[mt], bl[nt]);
                    mma_bf16(acc[mt][nt], al[mt], bh[nt]);
                }
        }
    }

    // epilogue: bias + tanh, direct stores
    const int er = lane >> 2, ec = (lane & 3) * 2;
    #pragma unroll
    for (int nt = 0; nt < 2; nt++) {
        const int col = n0 + warpN * 16 + nt * 8 + ec;
        const float2 bv = *(const float2*)&bias[col];
        #pragma unroll
        for (int mt = 0; mt < 4; mt++) {
            const int r0 = m0 + warpM * 64 + mt * 16 + er;
            float t00 = tanhf(acc[mt][nt][0] + bv.x);
            float t01 = tanhf(acc[mt][nt][1] + bv.y);
            float t10 = tanhf(acc[mt][nt][2] + bv.x);
            float t11 = tanhf(acc[mt][nt][3] + bv.y);
            *(float2*)&T[(size_t)r0 * N + col]        = make_float2(t00, t01);
            *(float2*)&T[(size_t)(r0 + 8) * N + col]  = make_float2(t10, t11);
            *(float2*)&Dd[(size_t)r0 * N + col]       = make_float2(1.f - t00*t00, 1.f - t01*t01);
            *(float2*)&Dd[(size_t)(r0 + 8) * N + col] = make_float2(1.f - t10*t10, 1.f - t11*t11);
        }
    }
}

// ---------------- layer2 split-K partial GEMM (M=1024, N=64, K=2048) ----------------
__global__ void gemm_l2_partial(const float* __restrict__ A, const float* __restrict__ Bw,
                                float* __restrict__ part) {
    const int BM = 64, BN = 64, BK = 16, TM = 4, TN = 4;
    __shared__ float As[BK][BM];
    __shared__ float Bs[BK][BN];
    const int tid  = threadIdx.x;
    const int tcol = tid % (BN / TN);
    const int trow = tid / (BN / TN);
    const int kp = blockIdx.x;
    const int m0 = blockIdx.y * BM;
    const int kbeg = kp * 256, kend = kbeg + 256;
    const int kmax_thr = (tcol * 4 + 4) * 32;

    float acc[TM][TN];
    #pragma unroll
    for (int i = 0; i < TM; i++)
        #pragma unroll
        for (int j = 0; j < TN; j++) acc[i][j] = 0.f;

    for (int k0 = kbeg; k0 < kend; k0 += BK) {
        #pragma unroll
        for (int idx = tid; idx < BM * BK; idx += 256) {
            int m = idx / BK, kk = idx % BK;
            As[kk][m] = A[(size_t)(m0 + m) * DH + k0 + kk];
        }
        #pragma unroll
        for (int idx = tid; idx < BN * BK; idx += 256) {
            int n = idx / BK, kk = idx % BK;
            Bs[kk][n] = Bw[(size_t)n * DH + k0 + kk];
        }
        __syncthreads();
        if (k0 < kmax_thr) {
            #pragma unroll
            for (int kk = 0; kk < BK; kk++) {
                float ar[TM], br[TN];
                #pragma unroll
                for (int i = 0; i < TM; i++) ar[i] = As[kk][trow * TM + i];
                #pragma unroll
                for (int j = 0; j < TN; j++) br[j] = Bs[kk][tcol * TN + j];
                #pragma unroll
                for (int i = 0; i < TM; i++)
                    #pragma unroll
                    for (int j = 0; j < TN; j++)
                        acc[i][j] = fmaf(ar[i], br[j], acc[i][j]);
            }
        }
        __syncthreads();
    }
    #pragma unroll
    for (int i = 0; i < TM; i++) {
        int m = m0 + trow * TM + i;
        #pragma unroll
        for (int j = 0; j < TN; j++) {
            int n = tcol * TN + j;
            part[(size_t)kp * BATCH * DIMN + (size_t)m * DIMN + n] = acc[i][j];
        }
    }
}

__global__ void l2_reduce(const float* __restrict__ part, const float* __restrict__ bias,
                          float* __restrict__ h3) {
    int idx = blockIdx.x * blockDim.x + threadIdx.x;
    int n = idx & (DIMN - 1);
    float s = bias[n];
    #pragma unroll
    for (int kp = 0; kp < 8; kp++) s += part[(size_t)kp * BATCH * DIMN + idx];
    h3[idx] = s;
}

// ---------------- Jacobian chain (linear domain) ----------------
__global__ void grad_kernel(const float* __restrict__ wn0, const float* __restrict__ w1d,
                            const float* __restrict__ wn2,
                            const float* __restrict__ d1, const float* __restrict__ d2,
                            const float* __restrict__ gate, int use_gate,
                            float* __restrict__ ldjc) {
    __shared__ float s_w1[HID][HID + 1];
    __shared__ float s_v0[HID];
    __shared__ float s_w2[HID];
    int i = blockIdx.x;
    int tid = threadIdx.x;
    for (int idx = tid; idx < HID * HID; idx += blockDim.x) {
        int r = idx >> 5, c = idx & 31;
        s_w1[r][c] = w1d[i * 1024 + r * 32 + c];
    }
    if (tid < HID) {
        s_v0[tid] = wn0[(size_t)(i * HID + tid) * DIMN + i];
        s_w2[tid] = wn2[(size_t)i * DH + i * HID + tid];
    }
    __syncthreads();
    int warp = tid >> 5, lane = tid & 31;
    int b = blockIdx.y * (blockDim.x >> 5) + warp;

    float u1 = s_v0[lane] * d1[(size_t)b * DH + i * HID + lane];
    float acc = 0.f;
    #pragma unroll
    for (int k = 0; k < HID; k++) {
        float uk = __shfl_sync(0xffffffffu, u1, k);
        acc = fmaf(s_w1[lane][k], uk, acc);
    }
    float term = s_w2[lane] * (acc * d2[(size_t)b * DH + i * HID + lane]);
    #pragma unroll
    for (int off = 16; off; off >>= 1) term += __shfl_down_sync(0xffffffffu, term, off);
    if (lane == 0) {
        float J = term;
        float c;
        if (use_gate) {
            float g = gate[0];
            c = log1pf(J * expf(g)) - log1pf(expf(g));
        } else {
            c = logf(J);
        }
        ldjc[(size_t)b * DIMN + i] = c;
    }
}

// ---------------- gate mix + reversal + ldj reduction / final density ----------------
__global__ void mix_kernel(const float* __restrict__ h3, const float* __restrict__ xin,
                           const float* __restrict__ ldjc, const float* __restrict__ gate,
                           int flow, float* __restrict__ xout, float* __restrict__ ldj,
                           float* __restrict__ out_final) {
    int warp = threadIdx.x >> 5, lane = threadIdx.x & 31;
    int b = blockIdx.x * (blockDim.x >> 5) + warp;
    float sum = ldjc[(size_t)b * DIMN + lane] + ldjc[(size_t)b * DIMN + 32 + lane];
    if (flow < 2) {
        float gv = gate[0];
        float s = 1.f / (1.f + expf(-gv));
        float o0 = s * h3[b * DIMN + lane]      + (1.f - s) * xin[b * DIMN + lane];
        float o1 = s * h3[b * DIMN + 32 + lane] + (1.f - s) * xin[b * DIMN + 32 + lane];
        xout[b * DIMN + (DIMN - 1 - lane)]        = o0;
        xout[b * DIMN + (DIMN - 1 - (32 + lane))] = o1;
    } else {
        float o0 = h3[b * DIMN + lane], o1 = h3[b * DIMN + 32 + lane];
        sum += -0.5f * (o0 * o0 + o1 * o1) - LOG2PI_F;
    }
    #pragma unroll
    for (int off = 16; off; off >>= 1) sum += __shfl_down_sync(0xffffffffu, sum, off);
    if (lane == 0) {
        if (flow == 0)      ldj[b] = sum;
        else if (flow == 1) ldj[b] += sum;
        else                out_final[b] = ldj[b] + sum;
    }
}

// ---------------- launch ----------------
extern "C" void kernel_launch(void* const* d_in, const int* in_sizes, int n_in,
                              void* d_out, int out_size) {
    const float* x = (const float*)d_in[0];
    const float* gates[2] = { (const float*)d_in[28], (const float*)d_in[29] };

    float *wn_base, *d1, *t2, *d2, *h3, *xa, *xb, *ldjc, *ldj, *part, *w1d;
    __nv_bfloat16 *w1h, *w1l, *t1h, *t1l;
    cudaGetSymbolAddress((void**)&wn_base, g_wn);
    cudaGetSymbolAddress((void**)&w1h,  g_w1h);
    cudaGetSymbolAddress((void**)&w1l,  g_w1l);
    cudaGetSymbolAddress((void**)&w1d,  g_w1d);
    cudaGetSymbolAddress((void**)&t1h,  g_t1h);
    cudaGetSymbolAddress((void**)&t1l,  g_t1l);
    cudaGetSymbolAddress((void**)&d1,   g_d1);
    cudaGetSymbolAddress((void**)&t2,   g_t2);
    cudaGetSymbolAddress((void**)&d2,   g_d2);
    cudaGetSymbolAddress((void**)&h3,   g_h3);
    cudaGetSymbolAddress((void**)&xa,   g_xa);
    cudaGetSymbolAddress((void**)&xb,   g_xb);
    cudaGetSymbolAddress((void**)&ldjc, g_ldjc);
    cudaGetSymbolAddress((void**)&ldj,  g_ldj);
    cudaGetSymbolAddress((void**)&part, g_part);

    const size_t SZ0 = (size_t)DH * DIMN;
    const size_t SZ1 = (size_t)DH * DH;
    const size_t SZ2 = (size_t)DIMN * DH;
    const size_t FSZ = SZ0 + SZ1 + SZ2;

    const int DYN_SMEM = 3 * 24576;
    cudaFuncSetAttribute(gemm_mma_l1, cudaFuncAttributeMaxDynamicSharedMemorySize, DYN_SMEM);

    // fused preprocessing: 3 launches for all flows
    PtrSet p0, p1, p2;
    for (int f = 0; f < 3; f++) {
        p0.W[f]  = (const float*)d_in[1 + f * 9 + 0];
        p0.dw[f] = (const float*)d_in[1 + f * 9 + 1];
        p1.W[f]  = (const float*)d_in[1 + f * 9 + 3];
        p1.dw[f] = (const float*)d_in[1 + f * 9 + 4];
        p2.W[f]  = (const float*)d_in[1 + f * 9 + 6];
        p2.dw[f] = (const float*)d_in[1 + f * 9 + 7];
    }
    prep0_fused<<<dim3(256, 3),  256>>>(p0, wn_base, FSZ);
    prep1_fused<<<dim3(DH, 3),   256, DH * sizeof(float)>>>(p1, w1h, w1l, w1d);
    prep2_fused<<<dim3(DIMN, 3), 256, DH * sizeof(float)>>>(p2, wn_base, FSZ, SZ0 + SZ1);

    const float* xcur = x;
    for (int f = 0; f < 3; f++) {
        float* wn0 = wn_base + f * FSZ;
        float* wn2 = wn0 + SZ0 + SZ1;
        const float* b0 = (const float*)d_in[1 + f * 9 + 2];
        const float* b1 = (const float*)d_in[1 + f * 9 + 5];
        const float* b2 = (const float*)d_in[1 + f * 9 + 8];

        gemm_l0<<<dim3(DH / 64, BATCH / 128), 256>>>(xcur, wn0, b0, t1h, t1l, d1, DIMN, DH);
        gemm_mma_l1<<<256, 256, DYN_SMEM>>>(
            t1h, t1l, w1h + f * SZ1, w1l + f * SZ1, b1, t2, d2);
        gemm_l2_partial<<<dim3(8, BATCH / 64), 256>>>(t2, wn2, part);
        l2_reduce<<<(BATCH * DIMN) / 256, 256>>>(part, b2, h3);

        grad_kernel<<<dim3(DIMN, BATCH / 8), 256>>>(
            wn0, w1d + f * 64 * 1024, wn2, d1, d2,
            (f < 2) ? gates[f] : nullptr, (f < 2) ? 1 : 0, ldjc);

        float* xnext = (f == 0) ? xa : xb;
        mix_kernel<<<BATCH / 8, 256>>>(
            h3, xcur, ldjc, (f < 2) ? gates[f] : nullptr, f,
            xnext, ldj, (float*)d_out);
        xcur = xnext;
    }
}